// round 4
// baseline (speedup 1.0000x reference)
#include <cuda_runtime.h>
#include <math.h>

#define D_DIM   768
#define R_DIM   64
#define E_NUM   4
#define NT      1029
#define BATCH   64
#define M_ROWS  (BATCH * NT)        /* 65856 */
#define T_TOKENS (BATCH * 1024)     /* 65536 MoE tokens */

/* scratch: h / "full" buffer (in-place MoE update), transposed expert weights */
__device__ float g_h[(size_t)M_ROWS * R_DIM];
__device__ float g_WeT[E_NUM * R_DIM * R_DIM];

__device__ __forceinline__ float gelu_exact(float v) {
    return 0.5f * v * (1.0f + erff(v * 0.70710678118654752f));
}

__device__ __forceinline__ unsigned f2tf32(float f) {
    unsigned u;
    asm("cvt.rna.tf32.f32 %0, %1;" : "=r"(u) : "f"(f));
    return u;
}

/* split f into tf32 hi + tf32 lo (3xTF32 scheme) */
__device__ __forceinline__ void tf32_split(float f, unsigned& hi, unsigned& lo) {
    hi = f2tf32(f);
    lo = f2tf32(f - __uint_as_float(hi));
}

#define MMA_TF32(C, A, B)                                                     \
    asm volatile(                                                             \
        "mma.sync.aligned.m16n8k8.row.col.f32.tf32.tf32.f32 "                 \
        "{%0,%1,%2,%3}, {%4,%5,%6,%7}, {%8,%9}, {%0,%1,%2,%3};"               \
        : "+f"((C)[0]), "+f"((C)[1]), "+f"((C)[2]), "+f"((C)[3])              \
        : "r"((A)[0]), "r"((A)[1]), "r"((A)[2]), "r"((A)[3]),                 \
          "r"((B)[0]), "r"((B)[1]))

/* swizzled index into a [rows x 64] word tile: 4-word granules XOR row&7 */
__device__ __forceinline__ int SW64(int row, int col) {
    return row * 64 + ((((col >> 2) ^ (row & 7)) << 2) | (col & 3));
}

/* ------------------------------------------------------------------ */
/* K0: WeT[e][r][s] = We[e][s][r]                                      */
__global__ void k0_transpose(const float* __restrict__ We) {
    int i = blockIdx.x * 256 + threadIdx.x;
    if (i < E_NUM * R_DIM * R_DIM) {
        int e = i >> 12;
        int r = (i >> 6) & 63;
        int s = i & 63;
        g_WeT[i] = We[(e << 12) + (s << 6) + r];
    }
}

/* ------------------------------------------------------------------ */
/* K1 (3xTF32): g_h[m][n] = gelu( X[m][:] . Wd[n][:] )                 */
/* CTA tile 128(M) x 64(N), K-step 32 (hi cols 0-31, lo cols 32-63).   */
__global__ __launch_bounds__(256) void k1_gemm_gelu(
    const float* __restrict__ X, const float* __restrict__ Wd)
{
    __shared__ unsigned Xs[128 * 64];   /* 32 KB */
    __shared__ unsigned Ws[64 * 64];    /* 16 KB */

    const int tid  = threadIdx.x;
    const int wid  = tid >> 5;
    const int lane = tid & 31;
    const int wm   = wid >> 1;           /* 0..3 */
    const int wn   = wid & 1;            /* 0..1 */
    const int r4   = lane >> 2;          /* 0..7 */
    const int c4   = lane & 3;           /* 0..3 */
    const int m0   = blockIdx.x * 128;

    float acc[2][4][4];
#pragma unroll
    for (int mt = 0; mt < 2; mt++)
#pragma unroll
        for (int nt = 0; nt < 4; nt++)
#pragma unroll
            for (int i = 0; i < 4; i++) acc[mt][nt][i] = 0.0f;

    for (int kt = 0; kt < D_DIM; kt += 32) {
        /* X tile: 128 rows x 32 k, split hi/lo */
#pragma unroll
        for (int j = 0; j < 4; j++) {
            int f = tid + 256 * j;
            int row = f >> 3;
            int kq = f & 7;
            int gr = m0 + row; if (gr >= M_ROWS) gr = M_ROWS - 1;
            float4 v = *(const float4*)(X + (size_t)gr * D_DIM + kt + kq * 4);
            unsigned h0,l0,h1,l1,h2,l2,h3,l3;
            tf32_split(v.x, h0, l0);
            tf32_split(v.y, h1, l1);
            tf32_split(v.z, h2, l2);
            tf32_split(v.w, h3, l3);
            int bh = SW64(row, kq * 4);
            int bl = SW64(row, kq * 4 + 32);
            Xs[bh+0]=h0; Xs[bh+1]=h1; Xs[bh+2]=h2; Xs[bh+3]=h3;
            Xs[bl+0]=l0; Xs[bl+1]=l1; Xs[bl+2]=l2; Xs[bl+3]=l3;
        }
        /* Wd tile: 64 rows(n) x 32 k, split hi/lo */
#pragma unroll
        for (int j = 0; j < 2; j++) {
            int f = tid + 256 * j;
            int n = f >> 3;
            int kq = f & 7;
            float4 v = *(const float4*)(Wd + n * D_DIM + kt + kq * 4);
            unsigned h0,l0,h1,l1,h2,l2,h3,l3;
            tf32_split(v.x, h0, l0);
            tf32_split(v.y, h1, l1);
            tf32_split(v.z, h2, l2);
            tf32_split(v.w, h3, l3);
            int bh = SW64(n, kq * 4);
            int bl = SW64(n, kq * 4 + 32);
            Ws[bh+0]=h0; Ws[bh+1]=h1; Ws[bh+2]=h2; Ws[bh+3]=h3;
            Ws[bl+0]=l0; Ws[bl+1]=l1; Ws[bl+2]=l2; Ws[bl+3]=l3;
        }
        __syncthreads();

#pragma unroll
        for (int kk = 0; kk < 4; kk++) {
            unsigned ah[2][4], al[2][4], bh[4][2], bl[4][2];
#pragma unroll
            for (int mt = 0; mt < 2; mt++) {
                int row = wm * 32 + mt * 16 + r4;
                int col = kk * 8 + c4;
                ah[mt][0] = Xs[SW64(row,     col)];
                ah[mt][1] = Xs[SW64(row + 8, col)];
                ah[mt][2] = Xs[SW64(row,     col + 4)];
                ah[mt][3] = Xs[SW64(row + 8, col + 4)];
                al[mt][0] = Xs[SW64(row,     col + 32)];
                al[mt][1] = Xs[SW64(row + 8, col + 32)];
                al[mt][2] = Xs[SW64(row,     col + 36)];
                al[mt][3] = Xs[SW64(row + 8, col + 36)];
            }
#pragma unroll
            for (int nt = 0; nt < 4; nt++) {
                int n = wn * 32 + nt * 8 + r4;
                bh[nt][0] = Ws[SW64(n, kk * 8 + c4)];
                bh[nt][1] = Ws[SW64(n, kk * 8 + c4 + 4)];
                bl[nt][0] = Ws[SW64(n, kk * 8 + c4 + 32)];
                bl[nt][1] = Ws[SW64(n, kk * 8 + c4 + 36)];
            }
#pragma unroll
            for (int mt = 0; mt < 2; mt++)
#pragma unroll
                for (int nt = 0; nt < 4; nt++) {
                    MMA_TF32(acc[mt][nt], al[mt], bh[nt]);
                    MMA_TF32(acc[mt][nt], ah[mt], bl[nt]);
                    MMA_TF32(acc[mt][nt], ah[mt], bh[nt]);
                }
        }
        __syncthreads();
    }

    /* epilogue: gelu, store to g_h[m][64] */
#pragma unroll
    for (int mt = 0; mt < 2; mt++) {
        int row0 = m0 + wm * 32 + mt * 16 + r4;
#pragma unroll
        for (int nt = 0; nt < 4; nt++) {
            int col = wn * 32 + nt * 8 + 2 * c4;
            if (row0 < M_ROWS) {
                float2 o;
                o.x = gelu_exact(acc[mt][nt][0]);
                o.y = gelu_exact(acc[mt][nt][1]);
                *(float2*)(g_h + (size_t)row0 * R_DIM + col) = o;
            }
            if (row0 + 8 < M_ROWS) {
                float2 o;
                o.x = gelu_exact(acc[mt][nt][2]);
                o.y = gelu_exact(acc[mt][nt][3]);
                *(float2*)(g_h + (size_t)(row0 + 8) * R_DIM + col) = o;
            }
        }
    }
}

/* ------------------------------------------------------------------ */
/* K2: in-place MoE on t tokens (n >= 5): h += w * (We[e] h + be[e])   */
__global__ __launch_bounds__(256) void k2_moe(
    const float* __restrict__ Wg, const float* __restrict__ be)
{
    __shared__ float hs[8][4][64];
    const int tid = threadIdx.x;
    const int w = tid >> 5;
    const int lane = tid & 31;
    float* hw = &hs[w][0][0];

    for (int it = 0; it < 8; it++) {
        int tbase = blockIdx.x * 256 + it * 32 + w * 4;
        int g[4];
#pragma unroll
        for (int j = 0; j < 4; j++) {
            int t = tbase + j;
            g[j] = (t >> 10) * NT + 5 + (t & 1023);
            float2 v = *(const float2*)(g_h + (size_t)g[j] * R_DIM + lane * 2);
            *(float2*)&hw[j * 64 + lane * 2] = v;
        }
        __syncwarp();

        int   esel[4];
        float wsel[4];
#pragma unroll
        for (int j = 0; j < 4; j++) {
            float h0 = hw[j * 64 + lane];
            float h1 = hw[j * 64 + 32 + lane];
            float l0 = h0 * Wg[lane]        + h1 * Wg[32 + lane];
            float l1 = h0 * Wg[64 + lane]   + h1 * Wg[96 + lane];
            float l2 = h0 * Wg[128 + lane]  + h1 * Wg[160 + lane];
            float l3 = h0 * Wg[192 + lane]  + h1 * Wg[224 + lane];
#pragma unroll
            for (int o = 16; o > 0; o >>= 1) {
                l0 += __shfl_xor_sync(0xffffffffu, l0, o);
                l1 += __shfl_xor_sync(0xffffffffu, l1, o);
                l2 += __shfl_xor_sync(0xffffffffu, l2, o);
                l3 += __shfl_xor_sync(0xffffffffu, l3, o);
            }
            float mx = fmaxf(fmaxf(l0, l1), fmaxf(l2, l3));
            float e0 = __expf(l0 - mx);
            float e1 = __expf(l1 - mx);
            float e2 = __expf(l2 - mx);
            float e3 = __expf(l3 - mx);
            float ssum = e0 + e1 + e2 + e3;
            int am = 0; float bv = l0; float ev = e0;
            if (l1 > bv) { bv = l1; am = 1; ev = e1; }
            if (l2 > bv) { bv = l2; am = 2; ev = e2; }
            if (l3 > bv) { bv = l3; am = 3; ev = e3; }
            esel[j] = am;
            wsel[j] = ev / ssum;
        }

        float acc[4][2];
#pragma unroll
        for (int j = 0; j < 4; j++) { acc[j][0] = 0.0f; acc[j][1] = 0.0f; }
        const float* wp[4];
#pragma unroll
        for (int j = 0; j < 4; j++) wp[j] = g_WeT + (esel[j] << 12);

#pragma unroll 8
        for (int r = 0; r < 64; r++) {
#pragma unroll
            for (int j = 0; j < 4; j++) {
                float hr = hw[j * 64 + r];
                float2 wv = *(const float2*)(wp[j] + (r << 6) + lane * 2);
                acc[j][0] = fmaf(hr, wv.x, acc[j][0]);
                acc[j][1] = fmaf(hr, wv.y, acc[j][1]);
            }
        }

#pragma unroll
        for (int j = 0; j < 4; j++) {
            int e = esel[j];
            float b0 = be[(e << 6) + lane * 2];
            float b1 = be[(e << 6) + lane * 2 + 1];
            float2 hv = *(float2*)&hw[j * 64 + lane * 2];
            float2 o;
            o.x = hv.x + wsel[j] * (acc[j][0] + b0);
            o.y = hv.y + wsel[j] * (acc[j][1] + b1);
            *(float2*)(g_h + (size_t)g[j] * R_DIM + lane * 2) = o;
        }
        __syncwarp();
    }
}

/* ------------------------------------------------------------------ */
/* K3 (3xTF32): out[m][d] = (full[m][:] . Wu[d][:]) * gamma[d]         */
/* CTA tile 128(M) x 64(N), K-step 32 x2, hi/lo split smem (48KB).     */
__global__ __launch_bounds__(256) void k3_gemm_out(
    const float* __restrict__ Wu, const float* __restrict__ gamma,
    float* __restrict__ out)
{
    __shared__ unsigned As[128 * 64];   /* 32 KB */
    __shared__ unsigned Bs[64 * 64];    /* 16 KB */

    const int tid  = threadIdx.x;
    const int wid  = tid >> 5;
    const int lane = tid & 31;
    const int wm   = wid >> 1;
    const int wn   = wid & 1;
    const int r4   = lane >> 2;
    const int c4   = lane & 3;
    const int m0   = blockIdx.x * 128;
    const int n0   = blockIdx.y * 64;

    float acc[2][4][4];
#pragma unroll
    for (int mt = 0; mt < 2; mt++)
#pragma unroll
        for (int nt = 0; nt < 4; nt++)
#pragma unroll
            for (int i = 0; i < 4; i++) acc[mt][nt][i] = 0.0f;

    for (int kh = 0; kh < 2; kh++) {
        int kt = kh * 32;
        /* A tile: 128 rows x 32 k from g_h, split hi/lo */
#pragma unroll
        for (int j = 0; j < 4; j++) {
            int f = tid + 256 * j;
            int row = f >> 3;
            int kq = f & 7;
            int gr = m0 + row; if (gr >= M_ROWS) gr = M_ROWS - 1;
            float4 v = *(const float4*)(g_h + (size_t)gr * R_DIM + kt + kq * 4);
            unsigned h0,l0,h1,l1,h2,l2,h3,l3;
            tf32_split(v.x, h0, l0);
            tf32_split(v.y, h1, l1);
            tf32_split(v.z, h2, l2);
            tf32_split(v.w, h3, l3);
            int bh = SW64(row, kq * 4);
            int bl = SW64(row, kq * 4 + 32);
            As[bh+0]=h0; As[bh+1]=h1; As[bh+2]=h2; As[bh+3]=h3;
            As[bl+0]=l0; As[bl+1]=l1; As[bl+2]=l2; As[bl+3]=l3;
        }
        /* B tile: 64 rows(n) x 32 k from Wu, split hi/lo */
#pragma unroll
        for (int j = 0; j < 2; j++) {
            int f = tid + 256 * j;
            int n = f >> 3;
            int kq = f & 7;
            float4 v = *(const float4*)(Wu + (size_t)(n0 + n) * R_DIM + kt + kq * 4);
            unsigned h0,l0,h1,l1,h2,l2,h3,l3;
            tf32_split(v.x, h0, l0);
            tf32_split(v.y, h1, l1);
            tf32_split(v.z, h2, l2);
            tf32_split(v.w, h3, l3);
            int bh = SW64(n, kq * 4);
            int bl = SW64(n, kq * 4 + 32);
            Bs[bh+0]=h0; Bs[bh+1]=h1; Bs[bh+2]=h2; Bs[bh+3]=h3;
            Bs[bl+0]=l0; Bs[bl+1]=l1; Bs[bl+2]=l2; Bs[bl+3]=l3;
        }
        __syncthreads();

#pragma unroll
        for (int kk = 0; kk < 4; kk++) {
            unsigned ah[2][4], al[2][4], bh[4][2], bl[4][2];
#pragma unroll
            for (int mt = 0; mt < 2; mt++) {
                int row = wm * 32 + mt * 16 + r4;
                int col = kk * 8 + c4;
                ah[mt][0] = As[SW64(row,     col)];
                ah[mt][1] = As[SW64(row + 8, col)];
                ah[mt][2] = As[SW64(row,     col + 4)];
                ah[mt][3] = As[SW64(row + 8, col + 4)];
                al[mt][0] = As[SW64(row,     col + 32)];
                al[mt][1] = As[SW64(row + 8, col + 32)];
                al[mt][2] = As[SW64(row,     col + 36)];
                al[mt][3] = As[SW64(row + 8, col + 36)];
            }
#pragma unroll
            for (int nt = 0; nt < 4; nt++) {
                int n = wn * 32 + nt * 8 + r4;
                bh[nt][0] = Bs[SW64(n, kk * 8 + c4)];
                bh[nt][1] = Bs[SW64(n, kk * 8 + c4 + 4)];
                bl[nt][0] = Bs[SW64(n, kk * 8 + c4 + 32)];
                bl[nt][1] = Bs[SW64(n, kk * 8 + c4 + 36)];
            }
#pragma unroll
            for (int mt = 0; mt < 2; mt++)
#pragma unroll
                for (int nt = 0; nt < 4; nt++) {
                    MMA_TF32(acc[mt][nt], al[mt], bh[nt]);
                    MMA_TF32(acc[mt][nt], ah[mt], bl[nt]);
                    MMA_TF32(acc[mt][nt], ah[mt], bh[nt]);
                }
        }
        __syncthreads();
    }

    /* epilogue: * gamma, store out[m][768] */
#pragma unroll
    for (int mt = 0; mt < 2; mt++) {
        int row0 = m0 + wm * 32 + mt * 16 + r4;
#pragma unroll
        for (int nt = 0; nt < 4; nt++) {
            int col = n0 + wn * 32 + nt * 8 + 2 * c4;
            float g0 = gamma[col];
            float g1 = gamma[col + 1];
            if (row0 < M_ROWS) {
                float2 o;
                o.x = acc[mt][nt][0] * g0;
                o.y = acc[mt][nt][1] * g1;
                *(float2*)(out + (size_t)row0 * D_DIM + col) = o;
            }
            if (row0 + 8 < M_ROWS) {
                float2 o;
                o.x = acc[mt][nt][2] * g0;
                o.y = acc[mt][nt][3] * g1;
                *(float2*)(out + (size_t)(row0 + 8) * D_DIM + col) = o;
            }
        }
    }
}

/* ------------------------------------------------------------------ */
extern "C" void kernel_launch(void* const* d_in, const int* in_sizes, int n_in,
                              void* d_out, int out_size) {
    const float* x     = (const float*)d_in[0];
    const float* Wd    = (const float*)d_in[1];
    const float* Wg    = (const float*)d_in[2];
    const float* We    = (const float*)d_in[3];
    const float* be    = (const float*)d_in[4];
    const float* Wu    = (const float*)d_in[5];
    const float* gamma = (const float*)d_in[6];
    float* out = (float*)d_out;

    k0_transpose<<<64, 256>>>(We);
    k1_gemm_gelu<<<(M_ROWS + 127) / 128, 256>>>(x, Wd);
    k2_moe<<<T_TOKENS / 256, 256>>>(Wg, be);
    dim3 g3((M_ROWS + 127) / 128, D_DIM / 64);
    k3_gemm_out<<<g3, 256>>>(Wu, gamma, out);
}

// round 5
// speedup vs baseline: 1.4127x; 1.4127x over previous
#include <cuda_runtime.h>
#include <math.h>

#define D_DIM   768
#define R_DIM   64
#define E_NUM   4
#define NT      1029
#define BATCH   64
#define M_ROWS  (BATCH * NT)        /* 65856 */

/* scratch: "full" buffer, transposed expert weights */
__device__ float g_h[(size_t)M_ROWS * R_DIM];
__device__ float g_WeT[E_NUM * R_DIM * R_DIM];

__device__ __forceinline__ float gelu_exact(float v) {
    return 0.5f * v * (1.0f + erff(v * 0.70710678118654752f));
}

__device__ __forceinline__ unsigned f2tf32(float f) {
    unsigned u;
    asm("cvt.rna.tf32.f32 %0, %1;" : "=r"(u) : "f"(f));
    return u;
}

__device__ __forceinline__ void tf32_split(float f, unsigned& hi, unsigned& lo) {
    hi = f2tf32(f);
    lo = f2tf32(f - __uint_as_float(hi));
}

#define MMA_TF32(C, A, B)                                                     \
    asm volatile(                                                             \
        "mma.sync.aligned.m16n8k8.row.col.f32.tf32.tf32.f32 "                 \
        "{%0,%1,%2,%3}, {%4,%5,%6,%7}, {%8,%9}, {%0,%1,%2,%3};"               \
        : "+f"((C)[0]), "+f"((C)[1]), "+f"((C)[2]), "+f"((C)[3])              \
        : "r"((A)[0]), "r"((A)[1]), "r"((A)[2]), "r"((A)[3]),                 \
          "r"((B)[0]), "r"((B)[1]))

/* swizzled store index into [rows x 64] word tile (generic, store-side only) */
__device__ __forceinline__ int SW64(int row, int col) {
    return row * 64 + ((((col >> 2) ^ (row & 7)) << 2) | (col & 3));
}

/* ------------------------------------------------------------------ */
/* K0: WeT[e][r][s] = We[e][s][r]                                      */
__global__ void k0_transpose(const float* __restrict__ We) {
    int i = blockIdx.x * 256 + threadIdx.x;
    if (i < E_NUM * R_DIM * R_DIM) {
        int e = i >> 12;
        int r = (i >> 6) & 63;
        int s = i & 63;
        g_WeT[i] = We[(e << 12) + (s << 6) + r];
    }
}

/* ------------------------------------------------------------------ */
/* K1 fused (3xTF32 GEMM + gelu + MoE):                                */
/*   h = gelu(X . Wd^T); then per-token top-1 MoE combine, write g_h.  */
/* CTA tile 128(M) x 64(N), K-step 32, hi/lo split smem.               */
#define HS 66
__global__ __launch_bounds__(256, 2) void k1_fused(
    const float* __restrict__ X, const float* __restrict__ Wd,
    const float* __restrict__ Wg, const float* __restrict__ be)
{
    __shared__ __align__(16) unsigned s_buf[12288];  /* 48 KB */
    unsigned* Xs = s_buf;            /* 128*64 words */
    unsigned* Ws = s_buf + 8192;     /* 64*64 words  */
    float*    Hs = (float*)s_buf;    /* 128*66 floats, reused post-GEMM */

    const int tid  = threadIdx.x;
    const int wid  = tid >> 5;
    const int lane = tid & 31;
    const int wm   = wid >> 1;           /* 0..3 */
    const int wn   = wid & 1;            /* 0..1 */
    const int r4   = lane >> 2;          /* 0..7 */
    const int c4   = lane & 3;           /* 0..3 */
    const int r4s  = r4 << 2;
    const int m0   = blockIdx.x * 128;

    /* per-thread fragment base indices (row&7 == r4 for all of these) */
    int arow[4], bb[4];
#pragma unroll
    for (int i = 0; i < 4; i++)
        arow[i] = (wm * 32 + r4 + i * 8) * 64 + c4;
#pragma unroll
    for (int nt = 0; nt < 4; nt++)
        bb[nt] = (wn * 32 + nt * 8 + r4) * 64 + c4;

    float acc[2][4][4];
#pragma unroll
    for (int mt = 0; mt < 2; mt++)
#pragma unroll
        for (int nt = 0; nt < 4; nt++)
#pragma unroll
            for (int i = 0; i < 4; i++) acc[mt][nt][i] = 0.0f;

    for (int kt = 0; kt < D_DIM; kt += 32) {
        /* X tile: 128 rows x 32 k, split hi/lo */
#pragma unroll
        for (int j = 0; j < 4; j++) {
            int f = tid + 256 * j;
            int row = f >> 3;
            int kq = f & 7;
            int gr = m0 + row; if (gr >= M_ROWS) gr = M_ROWS - 1;
            float4 v = *(const float4*)(X + (size_t)gr * D_DIM + kt + kq * 4);
            unsigned h0,l0,h1,l1,h2,l2,h3,l3;
            tf32_split(v.x, h0, l0);
            tf32_split(v.y, h1, l1);
            tf32_split(v.z, h2, l2);
            tf32_split(v.w, h3, l3);
            int bh_ = SW64(row, kq * 4);
            int bl_ = SW64(row, kq * 4 + 32);
            Xs[bh_+0]=h0; Xs[bh_+1]=h1; Xs[bh_+2]=h2; Xs[bh_+3]=h3;
            Xs[bl_+0]=l0; Xs[bl_+1]=l1; Xs[bl_+2]=l2; Xs[bl_+3]=l3;
        }
        /* Wd tile: 64 rows(n) x 32 k, split hi/lo */
#pragma unroll
        for (int j = 0; j < 2; j++) {
            int f = tid + 256 * j;
            int n = f >> 3;
            int kq = f & 7;
            float4 v = *(const float4*)(Wd + n * D_DIM + kt + kq * 4);
            unsigned h0,l0,h1,l1,h2,l2,h3,l3;
            tf32_split(v.x, h0, l0);
            tf32_split(v.y, h1, l1);
            tf32_split(v.z, h2, l2);
            tf32_split(v.w, h3, l3);
            int bh_ = SW64(n, kq * 4);
            int bl_ = SW64(n, kq * 4 + 32);
            Ws[bh_+0]=h0; Ws[bh_+1]=h1; Ws[bh_+2]=h2; Ws[bh_+3]=h3;
            Ws[bl_+0]=l0; Ws[bl_+1]=l1; Ws[bl_+2]=l2; Ws[bl_+3]=l3;
        }
        __syncthreads();

#pragma unroll
        for (int kk = 0; kk < 4; kk++) {
            const int g0 = ((kk * 2    ) << 2) ^ r4s;
            const int g1 = ((kk * 2 + 1) << 2) ^ r4s;
            const int g2 = ((kk * 2 + 8) << 2) ^ r4s;
            const int g3 = ((kk * 2 + 9) << 2) ^ r4s;
            unsigned ah[2][4], al[2][4], bhf[4][2], blf[4][2];
#pragma unroll
            for (int mt = 0; mt < 2; mt++) {
                ah[mt][0] = Xs[arow[2*mt]   + g0];
                ah[mt][1] = Xs[arow[2*mt+1] + g0];
                ah[mt][2] = Xs[arow[2*mt]   + g1];
                ah[mt][3] = Xs[arow[2*mt+1] + g1];
                al[mt][0] = Xs[arow[2*mt]   + g2];
                al[mt][1] = Xs[arow[2*mt+1] + g2];
                al[mt][2] = Xs[arow[2*mt]   + g3];
                al[mt][3] = Xs[arow[2*mt+1] + g3];
            }
#pragma unroll
            for (int nt = 0; nt < 4; nt++) {
                bhf[nt][0] = Ws[bb[nt] + g0];
                bhf[nt][1] = Ws[bb[nt] + g1];
                blf[nt][0] = Ws[bb[nt] + g2];
                blf[nt][1] = Ws[bb[nt] + g3];
            }
#pragma unroll
            for (int mt = 0; mt < 2; mt++)
#pragma unroll
                for (int nt = 0; nt < 4; nt++) {
                    MMA_TF32(acc[mt][nt], al[mt], bhf[nt]);
                    MMA_TF32(acc[mt][nt], ah[mt], blf[nt]);
                    MMA_TF32(acc[mt][nt], ah[mt], bhf[nt]);
                }
        }
        __syncthreads();
    }

    /* ---- epilogue phase 1: gelu -> Hs (smem), stride 66 ---- */
#pragma unroll
    for (int mt = 0; mt < 2; mt++) {
        int lr = wm * 32 + mt * 16 + r4;
#pragma unroll
        for (int nt = 0; nt < 4; nt++) {
            int col = wn * 32 + nt * 8 + 2 * c4;
            Hs[lr * HS + col]           = gelu_exact(acc[mt][nt][0]);
            Hs[lr * HS + col + 1]       = gelu_exact(acc[mt][nt][1]);
            Hs[(lr + 8) * HS + col]     = gelu_exact(acc[mt][nt][2]);
            Hs[(lr + 8) * HS + col + 1] = gelu_exact(acc[mt][nt][3]);
        }
    }
    __syncthreads();

    /* ---- epilogue phase 2: per-token MoE, write final to g_h ---- */
    /* warp wid handles local tokens [wid*16, wid*16+16), 4 at a time */
    for (int grp = 0; grp < 4; grp++) {
        const int tb = wid * 16 + grp * 4;

        int   esel[4];
        float wsel[4];
        int   grow[4];
        int   vmoe[4];   /* 0=invalid, 1=passthrough, 2=moe */
#pragma unroll
        for (int j = 0; j < 4; j++) {
            int t = tb + j;
            int gr = m0 + t;
            grow[j] = gr;
            if (gr >= M_ROWS) { vmoe[j] = 0; }
            else {
                int bidx = gr / NT;
                int nidx = gr - bidx * NT;
                vmoe[j] = (nidx >= 5) ? 2 : 1;
            }
            float h0 = Hs[t * HS + lane];
            float h1 = Hs[t * HS + 32 + lane];
            float l0 = h0 * __ldg(Wg + lane)       + h1 * __ldg(Wg + 32 + lane);
            float l1 = h0 * __ldg(Wg + 64 + lane)  + h1 * __ldg(Wg + 96 + lane);
            float l2 = h0 * __ldg(Wg + 128 + lane) + h1 * __ldg(Wg + 160 + lane);
            float l3 = h0 * __ldg(Wg + 192 + lane) + h1 * __ldg(Wg + 224 + lane);
#pragma unroll
            for (int o = 16; o > 0; o >>= 1) {
                l0 += __shfl_xor_sync(0xffffffffu, l0, o);
                l1 += __shfl_xor_sync(0xffffffffu, l1, o);
                l2 += __shfl_xor_sync(0xffffffffu, l2, o);
                l3 += __shfl_xor_sync(0xffffffffu, l3, o);
            }
            float mx = fmaxf(fmaxf(l0, l1), fmaxf(l2, l3));
            float e0 = __expf(l0 - mx);
            float e1 = __expf(l1 - mx);
            float e2 = __expf(l2 - mx);
            float e3 = __expf(l3 - mx);
            float ssum = e0 + e1 + e2 + e3;
            int am = 0; float bv = l0; float ev = e0;
            if (l1 > bv) { bv = l1; am = 1; ev = e1; }
            if (l2 > bv) { bv = l2; am = 2; ev = e2; }
            if (l3 > bv) { bv = l3; am = 3; ev = e3; }
            esel[j] = am;
            wsel[j] = ev / ssum;
        }

        float acc2[4][2];
#pragma unroll
        for (int j = 0; j < 4; j++) { acc2[j][0] = 0.0f; acc2[j][1] = 0.0f; }
        const float* wp[4];
#pragma unroll
        for (int j = 0; j < 4; j++) wp[j] = g_WeT + (esel[j] << 12);

#pragma unroll 8
        for (int r = 0; r < 64; r++) {
#pragma unroll
            for (int j = 0; j < 4; j++) {
                float hr = Hs[(tb + j) * HS + r];
                float2 wv = *(const float2*)(wp[j] + (r << 6) + lane * 2);
                acc2[j][0] = fmaf(hr, wv.x, acc2[j][0]);
                acc2[j][1] = fmaf(hr, wv.y, acc2[j][1]);
            }
        }

#pragma unroll
        for (int j = 0; j < 4; j++) {
            if (vmoe[j] == 0) continue;
            int t = tb + j;
            int e = esel[j];
            float s = (vmoe[j] == 2) ? wsel[j] : 0.0f;
            float b0 = __ldg(be + (e << 6) + lane * 2);
            float b1 = __ldg(be + (e << 6) + lane * 2 + 1);
            float2 hv;
            hv.x = Hs[t * HS + lane * 2];
            hv.y = Hs[t * HS + lane * 2 + 1];
            float2 o;
            o.x = hv.x + s * (acc2[j][0] + b0);
            o.y = hv.y + s * (acc2[j][1] + b1);
            *(float2*)(g_h + (size_t)grow[j] * R_DIM + lane * 2) = o;
        }
    }
}

/* ------------------------------------------------------------------ */
/* K3 (3xTF32): out[m][d] = (full[m][:] . Wu[d][:]) * gamma[d]         */
/* CTA tile 128(M) x 64(N), K-step 32 x2, hi/lo split smem (48KB).     */
__global__ __launch_bounds__(256, 2) void k3_gemm_out(
    const float* __restrict__ Wu, const float* __restrict__ gamma,
    float* __restrict__ out)
{
    __shared__ __align__(16) unsigned As[128 * 64];   /* 32 KB */
    __shared__ __align__(16) unsigned Bs[64 * 64];    /* 16 KB */

    const int tid  = threadIdx.x;
    const int wid  = tid >> 5;
    const int lane = tid & 31;
    const int wm   = wid >> 1;
    const int wn   = wid & 1;
    const int r4   = lane >> 2;
    const int c4   = lane & 3;
    const int r4s  = r4 << 2;
    const int m0   = blockIdx.x * 128;
    const int n0   = blockIdx.y * 64;

    int arow[4], bb[4];
#pragma unroll
    for (int i = 0; i < 4; i++)
        arow[i] = (wm * 32 + r4 + i * 8) * 64 + c4;
#pragma unroll
    for (int nt = 0; nt < 4; nt++)
        bb[nt] = (wn * 32 + nt * 8 + r4) * 64 + c4;

    float acc[2][4][4];
#pragma unroll
    for (int mt = 0; mt < 2; mt++)
#pragma unroll
        for (int nt = 0; nt < 4; nt++)
#pragma unroll
            for (int i = 0; i < 4; i++) acc[mt][nt][i] = 0.0f;

    for (int kh = 0; kh < 2; kh++) {
        int kt = kh * 32;
        /* A tile: 128 rows x 32 k from g_h, split hi/lo */
#pragma unroll
        for (int j = 0; j < 4; j++) {
            int f = tid + 256 * j;
            int row = f >> 3;
            int kq = f & 7;
            int gr = m0 + row; if (gr >= M_ROWS) gr = M_ROWS - 1;
            float4 v = *(const float4*)(g_h + (size_t)gr * R_DIM + kt + kq * 4);
            unsigned h0,l0,h1,l1,h2,l2,h3,l3;
            tf32_split(v.x, h0, l0);
            tf32_split(v.y, h1, l1);
            tf32_split(v.z, h2, l2);
            tf32_split(v.w, h3, l3);
            int bh_ = SW64(row, kq * 4);
            int bl_ = SW64(row, kq * 4 + 32);
            As[bh_+0]=h0; As[bh_+1]=h1; As[bh_+2]=h2; As[bh_+3]=h3;
            As[bl_+0]=l0; As[bl_+1]=l1; As[bl_+2]=l2; As[bl_+3]=l3;
        }
        /* B tile: 64 rows(n) x 32 k from Wu, split hi/lo */
#pragma unroll
        for (int j = 0; j < 2; j++) {
            int f = tid + 256 * j;
            int n = f >> 3;
            int kq = f & 7;
            float4 v = *(const float4*)(Wu + (size_t)(n0 + n) * R_DIM + kt + kq * 4);
            unsigned h0,l0,h1,l1,h2,l2,h3,l3;
            tf32_split(v.x, h0, l0);
            tf32_split(v.y, h1, l1);
            tf32_split(v.z, h2, l2);
            tf32_split(v.w, h3, l3);
            int bh_ = SW64(n, kq * 4);
            int bl_ = SW64(n, kq * 4 + 32);
            Bs[bh_+0]=h0; Bs[bh_+1]=h1; Bs[bh_+2]=h2; Bs[bh_+3]=h3;
            Bs[bl_+0]=l0; Bs[bl_+1]=l1; Bs[bl_+2]=l2; Bs[bl_+3]=l3;
        }
        __syncthreads();

#pragma unroll
        for (int kk = 0; kk < 4; kk++) {
            const int g0 = ((kk * 2    ) << 2) ^ r4s;
            const int g1 = ((kk * 2 + 1) << 2) ^ r4s;
            const int g2 = ((kk * 2 + 8) << 2) ^ r4s;
            const int g3 = ((kk * 2 + 9) << 2) ^ r4s;
            unsigned ah[2][4], al[2][4], bhf[4][2], blf[4][2];
#pragma unroll
            for (int mt = 0; mt < 2; mt++) {
                ah[mt][0] = As[arow[2*mt]   + g0];
                ah[mt][1] = As[arow[2*mt+1] + g0];
                ah[mt][2] = As[arow[2*mt]   + g1];
                ah[mt][3] = As[arow[2*mt+1] + g1];
                al[mt][0] = As[arow[2*mt]   + g2];
                al[mt][1] = As[arow[2*mt+1] + g2];
                al[mt][2] = As[arow[2*mt]   + g3];
                al[mt][3] = As[arow[2*mt+1] + g3];
            }
#pragma unroll
            for (int nt = 0; nt < 4; nt++) {
                bhf[nt][0] = Bs[bb[nt] + g0];
                bhf[nt][1] = Bs[bb[nt] + g1];
                blf[nt][0] = Bs[bb[nt] + g2];
                blf[nt][1] = Bs[bb[nt] + g3];
            }
#pragma unroll
            for (int mt = 0; mt < 2; mt++)
#pragma unroll
                for (int nt = 0; nt < 4; nt++) {
                    MMA_TF32(acc[mt][nt], al[mt], bhf[nt]);
                    MMA_TF32(acc[mt][nt], ah[mt], blf[nt]);
                    MMA_TF32(acc[mt][nt], ah[mt], bhf[nt]);
                }
        }
        __syncthreads();
    }

    /* epilogue: * gamma, store out[m][768] */
#pragma unroll
    for (int mt = 0; mt < 2; mt++) {
        int row0 = m0 + wm * 32 + mt * 16 + r4;
#pragma unroll
        for (int nt = 0; nt < 4; nt++) {
            int col = n0 + wn * 32 + nt * 8 + 2 * c4;
            float g0 = __ldg(gamma + col);
            float g1 = __ldg(gamma + col + 1);
            if (row0 < M_ROWS) {
                float2 o;
                o.x = acc[mt][nt][0] * g0;
                o.y = acc[mt][nt][1] * g1;
                *(float2*)(out + (size_t)row0 * D_DIM + col) = o;
            }
            if (row0 + 8 < M_ROWS) {
                float2 o;
                o.x = acc[mt][nt][2] * g0;
                o.y = acc[mt][nt][3] * g1;
                *(float2*)(out + (size_t)(row0 + 8) * D_DIM + col) = o;
            }
        }
    }
}

/* ------------------------------------------------------------------ */
extern "C" void kernel_launch(void* const* d_in, const int* in_sizes, int n_in,
                              void* d_out, int out_size) {
    const float* x     = (const float*)d_in[0];
    const float* Wd    = (const float*)d_in[1];
    const float* Wg    = (const float*)d_in[2];
    const float* We    = (const float*)d_in[3];
    const float* be    = (const float*)d_in[4];
    const float* Wu    = (const float*)d_in[5];
    const float* gamma = (const float*)d_in[6];
    float* out = (float*)d_out;

    k0_transpose<<<64, 256>>>(We);
    k1_fused<<<(M_ROWS + 127) / 128, 256>>>(x, Wd, Wg, be);
    dim3 g3((M_ROWS + 127) / 128, D_DIM / 64);
    k3_gemm_out<<<g3, 256>>>(Wu, gamma, out);
}

// round 6
// speedup vs baseline: 1.4871x; 1.0527x over previous
#include <cuda_runtime.h>
#include <math.h>

#define D_DIM   768
#define R_DIM   64
#define E_NUM   4
#define NT      1029
#define BATCH   64
#define M_ROWS  (BATCH * NT)        /* 65856 */

/* scratch: "full" buffer, transposed expert weights */
__device__ float g_h[(size_t)M_ROWS * R_DIM];
__device__ float g_WeT[E_NUM * R_DIM * R_DIM];

__device__ __forceinline__ float gelu_exact(float v) {
    return 0.5f * v * (1.0f + erff(v * 0.70710678118654752f));
}

__device__ __forceinline__ unsigned f2tf32(float f) {
    unsigned u;
    asm("cvt.rna.tf32.f32 %0, %1;" : "=r"(u) : "f"(f));
    return u;
}

__device__ __forceinline__ void split2(float f, unsigned& hi, unsigned& lo) {
    hi = f2tf32(f);
    lo = f2tf32(f - __uint_as_float(hi));
}

#define MMA_TF32(C, A, B)                                                     \
    asm volatile(                                                             \
        "mma.sync.aligned.m16n8k8.row.col.f32.tf32.tf32.f32 "                 \
        "{%0,%1,%2,%3}, {%4,%5,%6,%7}, {%8,%9}, {%0,%1,%2,%3};"               \
        : "+f"((C)[0]), "+f"((C)[1]), "+f"((C)[2]), "+f"((C)[3])              \
        : "r"((A)[0]), "r"((A)[1]), "r"((A)[2]), "r"((A)[3]),                 \
          "r"((B)[0]), "r"((B)[1]))

__device__ __forceinline__ void cp16(void* smem, const void* g) {
    unsigned sa = (unsigned)__cvta_generic_to_shared(smem);
    asm volatile("cp.async.ca.shared.global [%0], [%1], 16;" :: "r"(sa), "l"(g));
}
#define CP_COMMIT() asm volatile("cp.async.commit_group;")
#define CP_WAIT1()  asm volatile("cp.async.wait_group 1;")
#define CP_WAIT0()  asm volatile("cp.async.wait_group 0;")

/* ------------------------------------------------------------------ */
/* K0: WeT[e][r][s] = We[e][s][r]                                      */
__global__ void k0_transpose(const float* __restrict__ We) {
    int i = blockIdx.x * 256 + threadIdx.x;
    if (i < E_NUM * R_DIM * R_DIM) {
        int e = i >> 12;
        int r = (i >> 6) & 63;
        int s = i & 63;
        g_WeT[i] = We[(e << 12) + (s << 6) + r];
    }
}

/* ------------------------------------------------------------------ */
/* K1 fused: h = gelu(X.Wd^T) (3xTF32) + per-token top-1 MoE -> g_h.   */
/* 128(M)x64(N) tile, K-step 32, cp.async double-buffered raw tiles.   */
#define HS 66

__device__ __forceinline__ void k1_load(
    const float* __restrict__ X, const float* __restrict__ Wd,
    float* Xb, float* Wb, int m0, int kt, int tid)
{
#pragma unroll
    for (int j = 0; j < 4; j++) {
        int f = tid + 256 * j;
        int row = f >> 3, ck = f & 7;
        int gr = m0 + row; if (gr >= M_ROWS) gr = M_ROWS - 1;
        cp16(Xb + row * 32 + ((ck ^ (row & 7)) << 2),
             X + (size_t)gr * D_DIM + kt + ck * 4);
    }
#pragma unroll
    for (int j = 0; j < 2; j++) {
        int f = tid + 256 * j;
        int n = f >> 3, ck = f & 7;
        cp16(Wb + n * 32 + ((ck ^ (n & 7)) << 2),
             Wd + n * D_DIM + kt + ck * 4);
    }
}

__global__ __launch_bounds__(256, 2) void k1_fused(
    const float* __restrict__ X, const float* __restrict__ Wd,
    const float* __restrict__ Wg, const float* __restrict__ be)
{
    __shared__ __align__(16) float s_buf[12288];  /* 48 KB */
    float* Xb0 = s_buf;            /* 4096 floats */
    float* Xb1 = s_buf + 4096;
    float* Wb0 = s_buf + 8192;     /* 2048 floats */
    float* Wb1 = s_buf + 10240;
    float* Hs  = s_buf;            /* reused post-GEMM: 128*66 */

    const int tid  = threadIdx.x;
    const int wid  = tid >> 5;
    const int lane = tid & 31;
    const int wm   = wid >> 1;
    const int wn   = wid & 1;
    const int r4   = lane >> 2;
    const int c4   = lane & 3;
    const int m0   = blockIdx.x * 128;

    int arow[4], bbi[4];
#pragma unroll
    for (int i = 0; i < 4; i++)
        arow[i] = (wm * 32 + r4 + i * 8) * 32 + c4;
#pragma unroll
    for (int nt = 0; nt < 4; nt++)
        bbi[nt] = (wn * 32 + nt * 8 + r4) * 32 + c4;

    float acc[2][4][4];
#pragma unroll
    for (int mt = 0; mt < 2; mt++)
#pragma unroll
        for (int nt = 0; nt < 4; nt++)
#pragma unroll
            for (int i = 0; i < 4; i++) acc[mt][nt][i] = 0.0f;

    k1_load(X, Wd, Xb0, Wb0, m0, 0, tid);
    CP_COMMIT();

    for (int it = 0; it < 24; it++) {
        if (it < 23) {
            k1_load(X, Wd, (it & 1) ? Xb0 : Xb1, (it & 1) ? Wb0 : Wb1,
                    m0, (it + 1) * 32, tid);
            CP_COMMIT();
            CP_WAIT1();
        } else {
            CP_WAIT0();
        }
        __syncthreads();
        const float* Xc = (it & 1) ? Xb1 : Xb0;
        const float* Wc = (it & 1) ? Wb1 : Wb0;

#pragma unroll
        for (int kk = 0; kk < 4; kk++) {
            const int g0 = ((kk * 2)     ^ r4) << 2;
            const int g1 = ((kk * 2 + 1) ^ r4) << 2;
            unsigned ah[2][4], al[2][4], bh[4][2], bl[4][2];
#pragma unroll
            for (int mt = 0; mt < 2; mt++) {
                float f0 = Xc[arow[2*mt]   + g0];
                float f1 = Xc[arow[2*mt+1] + g0];
                float f2 = Xc[arow[2*mt]   + g1];
                float f3 = Xc[arow[2*mt+1] + g1];
                split2(f0, ah[mt][0], al[mt][0]);
                split2(f1, ah[mt][1], al[mt][1]);
                split2(f2, ah[mt][2], al[mt][2]);
                split2(f3, ah[mt][3], al[mt][3]);
            }
#pragma unroll
            for (int nt = 0; nt < 4; nt++) {
                float f0 = Wc[bbi[nt] + g0];
                float f1 = Wc[bbi[nt] + g1];
                split2(f0, bh[nt][0], bl[nt][0]);
                split2(f1, bh[nt][1], bl[nt][1]);
            }
#pragma unroll
            for (int mt = 0; mt < 2; mt++)
#pragma unroll
                for (int nt = 0; nt < 4; nt++) {
                    MMA_TF32(acc[mt][nt], al[mt], bh[nt]);
                    MMA_TF32(acc[mt][nt], ah[mt], bl[nt]);
                    MMA_TF32(acc[mt][nt], ah[mt], bh[nt]);
                }
        }
        __syncthreads();
    }

    /* ---- epilogue phase 1: gelu -> Hs (smem), stride 66 ---- */
#pragma unroll
    for (int mt = 0; mt < 2; mt++) {
        int lr = wm * 32 + mt * 16 + r4;
#pragma unroll
        for (int nt = 0; nt < 4; nt++) {
            int col = wn * 32 + nt * 8 + 2 * c4;
            Hs[lr * HS + col]           = gelu_exact(acc[mt][nt][0]);
            Hs[lr * HS + col + 1]       = gelu_exact(acc[mt][nt][1]);
            Hs[(lr + 8) * HS + col]     = gelu_exact(acc[mt][nt][2]);
            Hs[(lr + 8) * HS + col + 1] = gelu_exact(acc[mt][nt][3]);
        }
    }
    __syncthreads();

    /* ---- epilogue phase 2: per-token MoE, write final to g_h ---- */
    for (int grp = 0; grp < 4; grp++) {
        const int tb = wid * 16 + grp * 4;

        int   esel[4];
        float wsel[4];
        int   grow[4];
        int   vmoe[4];
#pragma unroll
        for (int j = 0; j < 4; j++) {
            int t = tb + j;
            int gr = m0 + t;
            grow[j] = gr;
            if (gr >= M_ROWS) { vmoe[j] = 0; }
            else {
                int bidx = gr / NT;
                int nidx = gr - bidx * NT;
                vmoe[j] = (nidx >= 5) ? 2 : 1;
            }
            float h0 = Hs[t * HS + lane];
            float h1 = Hs[t * HS + 32 + lane];
            float l0 = h0 * __ldg(Wg + lane)       + h1 * __ldg(Wg + 32 + lane);
            float l1 = h0 * __ldg(Wg + 64 + lane)  + h1 * __ldg(Wg + 96 + lane);
            float l2 = h0 * __ldg(Wg + 128 + lane) + h1 * __ldg(Wg + 160 + lane);
            float l3 = h0 * __ldg(Wg + 192 + lane) + h1 * __ldg(Wg + 224 + lane);
#pragma unroll
            for (int o = 16; o > 0; o >>= 1) {
                l0 += __shfl_xor_sync(0xffffffffu, l0, o);
                l1 += __shfl_xor_sync(0xffffffffu, l1, o);
                l2 += __shfl_xor_sync(0xffffffffu, l2, o);
                l3 += __shfl_xor_sync(0xffffffffu, l3, o);
            }
            float mx = fmaxf(fmaxf(l0, l1), fmaxf(l2, l3));
            float e0 = __expf(l0 - mx);
            float e1 = __expf(l1 - mx);
            float e2 = __expf(l2 - mx);
            float e3 = __expf(l3 - mx);
            float ssum = e0 + e1 + e2 + e3;
            int am = 0; float bv = l0; float ev = e0;
            if (l1 > bv) { bv = l1; am = 1; ev = e1; }
            if (l2 > bv) { bv = l2; am = 2; ev = e2; }
            if (l3 > bv) { bv = l3; am = 3; ev = e3; }
            esel[j] = am;
            wsel[j] = ev / ssum;
        }

        float acc2[4][2];
#pragma unroll
        for (int j = 0; j < 4; j++) { acc2[j][0] = 0.0f; acc2[j][1] = 0.0f; }
        const float* wp[4];
#pragma unroll
        for (int j = 0; j < 4; j++) wp[j] = g_WeT + (esel[j] << 12);

#pragma unroll 8
        for (int r = 0; r < 64; r++) {
#pragma unroll
            for (int j = 0; j < 4; j++) {
                float hr = Hs[(tb + j) * HS + r];
                float2 wv = *(const float2*)(wp[j] + (r << 6) + lane * 2);
                acc2[j][0] = fmaf(hr, wv.x, acc2[j][0]);
                acc2[j][1] = fmaf(hr, wv.y, acc2[j][1]);
            }
        }

#pragma unroll
        for (int j = 0; j < 4; j++) {
            if (vmoe[j] == 0) continue;
            int t = tb + j;
            int e = esel[j];
            float s = (vmoe[j] == 2) ? wsel[j] : 0.0f;
            float b0 = __ldg(be + (e << 6) + lane * 2);
            float b1 = __ldg(be + (e << 6) + lane * 2 + 1);
            float2 hv;
            hv.x = Hs[t * HS + lane * 2];
            hv.y = Hs[t * HS + lane * 2 + 1];
            float2 o;
            o.x = hv.x + s * (acc2[j][0] + b0);
            o.y = hv.y + s * (acc2[j][1] + b1);
            *(float2*)(g_h + (size_t)grow[j] * R_DIM + lane * 2) = o;
        }
    }
}

/* ------------------------------------------------------------------ */
/* K3: out[m][d] = (full[m][:] . Wu[d][:]) * gamma[d]  (3xTF32)        */
/* A (g_h) 128x64 split-resident (64KB); loop 12 n-blocks of 64 cols;  */
/* B raw double-buffered via cp.async (2x16KB). Dynamic smem 96KB.     */
#define K3_SMEM (96 * 1024)
__global__ __launch_bounds__(256, 2) void k3_gemm_out(
    const float* __restrict__ Wu, const float* __restrict__ gamma,
    float* __restrict__ out)
{
    extern __shared__ __align__(16) unsigned dsm[];
    unsigned* As  = dsm;                        /* 128*128 words = 64 KB */
    float*    Br0 = (float*)(dsm + 16384);      /* 4096 floats = 16 KB  */
    float*    Br1 = Br0 + 4096;

    const int tid  = threadIdx.x;
    const int wid  = tid >> 5;
    const int lane = tid & 31;
    const int wm   = wid >> 1;
    const int wn   = wid & 1;
    const int r4   = lane >> 2;
    const int c4   = lane & 3;
    const int m0   = blockIdx.x * 128;

    int arow[4], bbi[4];
#pragma unroll
    for (int i = 0; i < 4; i++)
        arow[i] = (wm * 32 + r4 + i * 8) * 128 + c4;
#pragma unroll
    for (int nt = 0; nt < 4; nt++)
        bbi[nt] = (wn * 32 + nt * 8 + r4) * 64 + c4;

    /* B prefetch for n-block nb into buffer */
    auto loadB = [&](int nb, float* buf) {
#pragma unroll
        for (int j = 0; j < 4; j++) {
            int f = tid + 256 * j;
            int row = f >> 4, ck = f & 15;
            cp16(buf + row * 64 + ((ck ^ (row & 7)) << 2),
                 Wu + (size_t)(nb * 64 + row) * R_DIM + ck * 4);
        }
    };

    /* A load + split once: 128 rows x 64 k -> hi cols 0-63, lo 64-127 */
#pragma unroll
    for (int j = 0; j < 8; j++) {
        int f = tid + 256 * j;
        int row = f >> 4, kq = f & 15;
        int gr = m0 + row; if (gr >= M_ROWS) gr = M_ROWS - 1;
        float4 v = *(const float4*)(g_h + (size_t)gr * R_DIM + kq * 4);
        unsigned h0,l0,h1,l1,h2,l2,h3,l3;
        split2(v.x, h0, l0); split2(v.y, h1, l1);
        split2(v.z, h2, l2); split2(v.w, h3, l3);
        int bh_ = row * 128 + ((kq        ^ (row & 7)) << 2);
        int bl_ = row * 128 + (((16 + kq) ^ (row & 7)) << 2);
        As[bh_+0]=h0; As[bh_+1]=h1; As[bh_+2]=h2; As[bh_+3]=h3;
        As[bl_+0]=l0; As[bl_+1]=l1; As[bl_+2]=l2; As[bl_+3]=l3;
    }
    loadB(0, Br0);
    CP_COMMIT();

    for (int nb = 0; nb < 12; nb++) {
        if (nb < 11) {
            loadB(nb + 1, (nb & 1) ? Br0 : Br1);
            CP_COMMIT();
            CP_WAIT1();
        } else {
            CP_WAIT0();
        }
        __syncthreads();
        const float* Bc = (nb & 1) ? Br1 : Br0;

        float acc[2][4][4];
#pragma unroll
        for (int mt = 0; mt < 2; mt++)
#pragma unroll
            for (int nt = 0; nt < 4; nt++)
#pragma unroll
                for (int i = 0; i < 4; i++) acc[mt][nt][i] = 0.0f;

#pragma unroll
        for (int kk = 0; kk < 8; kk++) {
            const int g0 = ((kk * 2)     ^ r4) << 2;
            const int g1 = ((kk * 2 + 1) ^ r4) << 2;
            unsigned ah[2][4], al[2][4], bh[4][2], bl[4][2];
#pragma unroll
            for (int mt = 0; mt < 2; mt++) {
                ah[mt][0] = As[arow[2*mt]   + g0];
                ah[mt][1] = As[arow[2*mt+1] + g0];
                ah[mt][2] = As[arow[2*mt]   + g1];
                ah[mt][3] = As[arow[2*mt+1] + g1];
                al[mt][0] = As[arow[2*mt]   + g0 + 64];
                al[mt][1] = As[arow[2*mt+1] + g0 + 64];
                al[mt][2] = As[arow[2*mt]   + g1 + 64];
                al[mt][3] = As[arow[2*mt+1] + g1 + 64];
            }
#pragma unroll
            for (int nt = 0; nt < 4; nt++) {
                float f0 = Bc[bbi[nt] + g0];
                float f1 = Bc[bbi[nt] + g1];
                split2(f0, bh[nt][0], bl[nt][0]);
                split2(f1, bh[nt][1], bl[nt][1]);
            }
#pragma unroll
            for (int mt = 0; mt < 2; mt++)
#pragma unroll
                for (int nt = 0; nt < 4; nt++) {
                    MMA_TF32(acc[mt][nt], al[mt], bh[nt]);
                    MMA_TF32(acc[mt][nt], ah[mt], bl[nt]);
                    MMA_TF32(acc[mt][nt], ah[mt], bh[nt]);
                }
        }

        /* epilogue for this n-block: * gamma, store out */
        int n0 = nb * 64;
#pragma unroll
        for (int mt = 0; mt < 2; mt++) {
            int row0 = m0 + wm * 32 + mt * 16 + r4;
#pragma unroll
            for (int nt = 0; nt < 4; nt++) {
                int col = n0 + wn * 32 + nt * 8 + 2 * c4;
                float g0 = __ldg(gamma + col);
                float g1 = __ldg(gamma + col + 1);
                if (row0 < M_ROWS) {
                    float2 o;
                    o.x = acc[mt][nt][0] * g0;
                    o.y = acc[mt][nt][1] * g1;
                    *(float2*)(out + (size_t)row0 * D_DIM + col) = o;
                }
                if (row0 + 8 < M_ROWS) {
                    float2 o;
                    o.x = acc[mt][nt][2] * g0;
                    o.y = acc[mt][nt][3] * g1;
                    *(float2*)(out + (size_t)(row0 + 8) * D_DIM + col) = o;
                }
            }
        }
        __syncthreads();
    }
}

/* ------------------------------------------------------------------ */
extern "C" void kernel_launch(void* const* d_in, const int* in_sizes, int n_in,
                              void* d_out, int out_size) {
    const float* x     = (const float*)d_in[0];
    const float* Wd    = (const float*)d_in[1];
    const float* Wg    = (const float*)d_in[2];
    const float* We    = (const float*)d_in[3];
    const float* be    = (const float*)d_in[4];
    const float* Wu    = (const float*)d_in[5];
    const float* gamma = (const float*)d_in[6];
    float* out = (float*)d_out;

    cudaFuncSetAttribute(k3_gemm_out,
                         cudaFuncAttributeMaxDynamicSharedMemorySize, K3_SMEM);

    k0_transpose<<<64, 256>>>(We);
    k1_fused<<<(M_ROWS + 127) / 128, 256>>>(x, Wd, Wg, be);
    k3_gemm_out<<<(M_ROWS + 127) / 128, 256, K3_SMEM>>>(Wu, gamma, out);
}

// round 7
// speedup vs baseline: 1.7355x; 1.1671x over previous
#include <cuda_runtime.h>
#include <cuda_bf16.h>
#include <math.h>

#define D_DIM   768
#define R_DIM   64
#define E_NUM   4
#define NT      1029
#define BATCH   64
#define M_ROWS  (BATCH * NT)        /* 65856 */

/* scratch: "full" buffer, transposed expert weights, pre-split packed Wu */
__device__ float    g_h[(size_t)M_ROWS * R_DIM];
__device__ float    g_WeT[E_NUM * R_DIM * R_DIM];
__device__ unsigned g_WuP[D_DIM * 64];   /* [d][64w]: hi words 0-31, lo 32-63 */

__device__ __forceinline__ float gelu_exact(float v) {
    return 0.5f * v * (1.0f + erff(v * 0.70710678118654752f));
}

__device__ __forceinline__ unsigned f2tf32(float f) {
    unsigned u;
    asm("cvt.rna.tf32.f32 %0, %1;" : "=r"(u) : "f"(f));
    return u;
}

__device__ __forceinline__ void split2(float f, unsigned& hi, unsigned& lo) {
    hi = f2tf32(f);
    lo = f2tf32(f - __uint_as_float(hi));
}

/* bf16 split+pack: two floats -> hi word (bf16x2) + lo word (residual) */
__device__ __forceinline__ void bfsplit2(float f0, float f1,
                                         unsigned& hw, unsigned& lw) {
    __nv_bfloat16 h0 = __float2bfloat16_rn(f0);
    __nv_bfloat16 h1 = __float2bfloat16_rn(f1);
    float r0 = f0 - __bfloat162float(h0);
    float r1 = f1 - __bfloat162float(h1);
    __nv_bfloat16 l0 = __float2bfloat16_rn(r0);
    __nv_bfloat16 l1 = __float2bfloat16_rn(r1);
    __nv_bfloat162 hv = __halves2bfloat162(h0, h1);
    __nv_bfloat162 lv = __halves2bfloat162(l0, l1);
    hw = *(unsigned*)&hv;
    lw = *(unsigned*)&lv;
}

#define MMA_TF32(C, A, B)                                                     \
    asm volatile(                                                             \
        "mma.sync.aligned.m16n8k8.row.col.f32.tf32.tf32.f32 "                 \
        "{%0,%1,%2,%3}, {%4,%5,%6,%7}, {%8,%9}, {%0,%1,%2,%3};"               \
        : "+f"((C)[0]), "+f"((C)[1]), "+f"((C)[2]), "+f"((C)[3])              \
        : "r"((A)[0]), "r"((A)[1]), "r"((A)[2]), "r"((A)[3]),                 \
          "r"((B)[0]), "r"((B)[1]))

#define MMA_BF16(C, A, B)                                                     \
    asm volatile(                                                             \
        "mma.sync.aligned.m16n8k16.row.col.f32.bf16.bf16.f32 "                \
        "{%0,%1,%2,%3}, {%4,%5,%6,%7}, {%8,%9}, {%0,%1,%2,%3};"               \
        : "+f"((C)[0]), "+f"((C)[1]), "+f"((C)[2]), "+f"((C)[3])              \
        : "r"((A)[0]), "r"((A)[1]), "r"((A)[2]), "r"((A)[3]),                 \
          "r"((B)[0]), "r"((B)[1]))

__device__ __forceinline__ void cp16(void* smem, const void* g) {
    unsigned sa = (unsigned)__cvta_generic_to_shared(smem);
    asm volatile("cp.async.ca.shared.global [%0], [%1], 16;" :: "r"(sa), "l"(g));
}
#define CP_COMMIT() asm volatile("cp.async.commit_group;")
#define CP_WAIT1()  asm volatile("cp.async.wait_group 1;")
#define CP_WAIT0()  asm volatile("cp.async.wait_group 0;")

/* ------------------------------------------------------------------ */
/* K0: WeT[e][r][s] = We[e][s][r]                                      */
__global__ void k0_transpose(const float* __restrict__ We) {
    int i = blockIdx.x * 256 + threadIdx.x;
    if (i < E_NUM * R_DIM * R_DIM) {
        int e = i >> 12;
        int r = (i >> 6) & 63;
        int s = i & 63;
        g_WeT[i] = We[(e << 12) + (s << 6) + r];
    }
}

/* K0b: Wu[d][64] fp32 -> g_WuP[d][64w] packed bf16 hi/lo               */
__global__ void k0b_convert(const float* __restrict__ Wu) {
    int i = blockIdx.x * 256 + threadIdx.x;   /* granule id: 768*8 */
    if (i >= D_DIM * 8) return;
    int d = i >> 3;
    int g = i & 7;
    const float* src = Wu + d * 64 + g * 8;
    float4 v0 = *(const float4*)(src);
    float4 v1 = *(const float4*)(src + 4);
    unsigned h0,l0,h1,l1,h2,l2,h3,l3;
    bfsplit2(v0.x, v0.y, h0, l0);
    bfsplit2(v0.z, v0.w, h1, l1);
    bfsplit2(v1.x, v1.y, h2, l2);
    bfsplit2(v1.z, v1.w, h3, l3);
    unsigned* dst = g_WuP + d * 64;
    *(uint4*)(dst + g * 4)      = make_uint4(h0, h1, h2, h3);
    *(uint4*)(dst + 32 + g * 4) = make_uint4(l0, l1, l2, l3);
}

/* ------------------------------------------------------------------ */
/* K1 fused: h = gelu(X.Wd^T) (3xTF32) + per-token top-1 MoE -> g_h.   */
#define HS 66

__device__ __forceinline__ void k1_load(
    const float* __restrict__ X, const float* __restrict__ Wd,
    float* Xb, float* Wb, int m0, int kt, int tid)
{
#pragma unroll
    for (int j = 0; j < 4; j++) {
        int f = tid + 256 * j;
        int row = f >> 3, ck = f & 7;
        int gr = m0 + row; if (gr >= M_ROWS) gr = M_ROWS - 1;
        cp16(Xb + row * 32 + ((ck ^ (row & 7)) << 2),
             X + (size_t)gr * D_DIM + kt + ck * 4);
    }
#pragma unroll
    for (int j = 0; j < 2; j++) {
        int f = tid + 256 * j;
        int n = f >> 3, ck = f & 7;
        cp16(Wb + n * 32 + ((ck ^ (n & 7)) << 2),
             Wd + n * D_DIM + kt + ck * 4);
    }
}

__global__ __launch_bounds__(256, 2) void k1_fused(
    const float* __restrict__ X, const float* __restrict__ Wd,
    const float* __restrict__ Wg, const float* __restrict__ be)
{
    __shared__ __align__(16) float s_buf[12288];  /* 48 KB */
    float* Xb0 = s_buf;
    float* Xb1 = s_buf + 4096;
    float* Wb0 = s_buf + 8192;
    float* Wb1 = s_buf + 10240;
    float* Hs  = s_buf;

    const int tid  = threadIdx.x;
    const int wid  = tid >> 5;
    const int lane = tid & 31;
    const int wm   = wid >> 1;
    const int wn   = wid & 1;
    const int r4   = lane >> 2;
    const int c4   = lane & 3;
    const int m0   = blockIdx.x * 128;

    int arow[4], bbi[4];
#pragma unroll
    for (int i = 0; i < 4; i++)
        arow[i] = (wm * 32 + r4 + i * 8) * 32 + c4;
#pragma unroll
    for (int nt = 0; nt < 4; nt++)
        bbi[nt] = (wn * 32 + nt * 8 + r4) * 32 + c4;

    float acc[2][4][4];
#pragma unroll
    for (int mt = 0; mt < 2; mt++)
#pragma unroll
        for (int nt = 0; nt < 4; nt++)
#pragma unroll
            for (int i = 0; i < 4; i++) acc[mt][nt][i] = 0.0f;

    k1_load(X, Wd, Xb0, Wb0, m0, 0, tid);
    CP_COMMIT();

    for (int it = 0; it < 24; it++) {
        if (it < 23) {
            k1_load(X, Wd, (it & 1) ? Xb0 : Xb1, (it & 1) ? Wb0 : Wb1,
                    m0, (it + 1) * 32, tid);
            CP_COMMIT();
            CP_WAIT1();
        } else {
            CP_WAIT0();
        }
        __syncthreads();
        const float* Xc = (it & 1) ? Xb1 : Xb0;
        const float* Wc = (it & 1) ? Wb1 : Wb0;

#pragma unroll
        for (int kk = 0; kk < 4; kk++) {
            const int g0 = ((kk * 2)     ^ r4) << 2;
            const int g1 = ((kk * 2 + 1) ^ r4) << 2;
            unsigned ah[2][4], al[2][4], bh[4][2], bl[4][2];
#pragma unroll
            for (int mt = 0; mt < 2; mt++) {
                float f0 = Xc[arow[2*mt]   + g0];
                float f1 = Xc[arow[2*mt+1] + g0];
                float f2 = Xc[arow[2*mt]   + g1];
                float f3 = Xc[arow[2*mt+1] + g1];
                split2(f0, ah[mt][0], al[mt][0]);
                split2(f1, ah[mt][1], al[mt][1]);
                split2(f2, ah[mt][2], al[mt][2]);
                split2(f3, ah[mt][3], al[mt][3]);
            }
#pragma unroll
            for (int nt = 0; nt < 4; nt++) {
                float f0 = Wc[bbi[nt] + g0];
                float f1 = Wc[bbi[nt] + g1];
                split2(f0, bh[nt][0], bl[nt][0]);
                split2(f1, bh[nt][1], bl[nt][1]);
            }
#pragma unroll
            for (int mt = 0; mt < 2; mt++)
#pragma unroll
                for (int nt = 0; nt < 4; nt++) {
                    MMA_TF32(acc[mt][nt], al[mt], bh[nt]);
                    MMA_TF32(acc[mt][nt], ah[mt], bl[nt]);
                    MMA_TF32(acc[mt][nt], ah[mt], bh[nt]);
                }
        }
        __syncthreads();
    }

    /* ---- epilogue phase 1: gelu -> Hs (smem), stride 66 ---- */
#pragma unroll
    for (int mt = 0; mt < 2; mt++) {
        int lr = wm * 32 + mt * 16 + r4;
#pragma unroll
        for (int nt = 0; nt < 4; nt++) {
            int col = wn * 32 + nt * 8 + 2 * c4;
            Hs[lr * HS + col]           = gelu_exact(acc[mt][nt][0]);
            Hs[lr * HS + col + 1]       = gelu_exact(acc[mt][nt][1]);
            Hs[(lr + 8) * HS + col]     = gelu_exact(acc[mt][nt][2]);
            Hs[(lr + 8) * HS + col + 1] = gelu_exact(acc[mt][nt][3]);
        }
    }
    __syncthreads();

    /* ---- epilogue phase 2: per-token MoE, write final to g_h ---- */
    for (int grp = 0; grp < 4; grp++) {
        const int tb = wid * 16 + grp * 4;

        int   esel[4];
        float wsel[4];
        int   grow[4];
        int   vmoe[4];
#pragma unroll
        for (int j = 0; j < 4; j++) {
            int t = tb + j;
            int gr = m0 + t;
            grow[j] = gr;
            if (gr >= M_ROWS) { vmoe[j] = 0; }
            else {
                int bidx = gr / NT;
                int nidx = gr - bidx * NT;
                vmoe[j] = (nidx >= 5) ? 2 : 1;
            }
            float h0 = Hs[t * HS + lane];
            float h1 = Hs[t * HS + 32 + lane];
            float l0 = h0 * __ldg(Wg + lane)       + h1 * __ldg(Wg + 32 + lane);
            float l1 = h0 * __ldg(Wg + 64 + lane)  + h1 * __ldg(Wg + 96 + lane);
            float l2 = h0 * __ldg(Wg + 128 + lane) + h1 * __ldg(Wg + 160 + lane);
            float l3 = h0 * __ldg(Wg + 192 + lane) + h1 * __ldg(Wg + 224 + lane);
#pragma unroll
            for (int o = 16; o > 0; o >>= 1) {
                l0 += __shfl_xor_sync(0xffffffffu, l0, o);
                l1 += __shfl_xor_sync(0xffffffffu, l1, o);
                l2 += __shfl_xor_sync(0xffffffffu, l2, o);
                l3 += __shfl_xor_sync(0xffffffffu, l3, o);
            }
            float mx = fmaxf(fmaxf(l0, l1), fmaxf(l2, l3));
            float e0 = __expf(l0 - mx);
            float e1 = __expf(l1 - mx);
            float e2 = __expf(l2 - mx);
            float e3 = __expf(l3 - mx);
            float ssum = e0 + e1 + e2 + e3;
            int am = 0; float bv = l0; float ev = e0;
            if (l1 > bv) { bv = l1; am = 1; ev = e1; }
            if (l2 > bv) { bv = l2; am = 2; ev = e2; }
            if (l3 > bv) { bv = l3; am = 3; ev = e3; }
            esel[j] = am;
            wsel[j] = ev / ssum;
        }

        float acc2[4][2];
#pragma unroll
        for (int j = 0; j < 4; j++) { acc2[j][0] = 0.0f; acc2[j][1] = 0.0f; }
        const float* wp[4];
#pragma unroll
        for (int j = 0; j < 4; j++) wp[j] = g_WeT + (esel[j] << 12);

#pragma unroll 8
        for (int r = 0; r < 64; r++) {
#pragma unroll
            for (int j = 0; j < 4; j++) {
                float hr = Hs[(tb + j) * HS + r];
                float2 wv = *(const float2*)(wp[j] + (r << 6) + lane * 2);
                acc2[j][0] = fmaf(hr, wv.x, acc2[j][0]);
                acc2[j][1] = fmaf(hr, wv.y, acc2[j][1]);
            }
        }

#pragma unroll
        for (int j = 0; j < 4; j++) {
            if (vmoe[j] == 0) continue;
            int t = tb + j;
            int e = esel[j];
            float s = (vmoe[j] == 2) ? wsel[j] : 0.0f;
            float b0 = __ldg(be + (e << 6) + lane * 2);
            float b1 = __ldg(be + (e << 6) + lane * 2 + 1);
            float2 hv;
            hv.x = Hs[t * HS + lane * 2];
            hv.y = Hs[t * HS + lane * 2 + 1];
            float2 o;
            o.x = hv.x + s * (acc2[j][0] + b0);
            o.y = hv.y + s * (acc2[j][1] + b1);
            *(float2*)(g_h + (size_t)grow[j] * R_DIM + lane * 2) = o;
        }
    }
}

/* ------------------------------------------------------------------ */
/* K3 (3-term bf16 m16n8k16): out = (full . Wu^T) * gamma              */
/* A (g_h) pre-split packed bf16 resident (32KB); B from g_WuP via     */
/* cp.async double buffer (2x16KB). Dynamic smem 64KB.                 */
#define K3_SMEM (64 * 1024)
__global__ __launch_bounds__(256, 2) void k3_gemm_out(
    const float* __restrict__ gamma, float* __restrict__ out)
{
    extern __shared__ __align__(16) unsigned dsm[];
    unsigned* As  = dsm;              /* 128 rows x 64 words = 32 KB */
    unsigned* Br0 = dsm + 8192;       /* 64 rows x 64 words = 16 KB  */
    unsigned* Br1 = dsm + 12288;

    const int tid  = threadIdx.x;
    const int wid  = tid >> 5;
    const int lane = tid & 31;
    const int wm   = wid >> 1;
    const int wn   = wid & 1;
    const int r4   = lane >> 2;
    const int c4   = lane & 3;
    const int m0   = blockIdx.x * 128;

    int arow[4], bbi[4];
#pragma unroll
    for (int i = 0; i < 4; i++)
        arow[i] = (wm * 32 + r4 + i * 8) * 64 + c4;
#pragma unroll
    for (int nt = 0; nt < 4; nt++)
        bbi[nt] = (wn * 32 + nt * 8 + r4) * 64 + c4;

    /* B prefetch: packed bf16 granules, swizzled dest */
    auto loadB = [&](int nb, unsigned* buf) {
#pragma unroll
        for (int j = 0; j < 4; j++) {
            int f = tid + 256 * j;
            int row = f >> 4, g = f & 15;
            cp16(buf + row * 64 + ((g ^ (row & 7)) << 2),
                 g_WuP + (size_t)(nb * 64 + row) * 64 + g * 4);
        }
    };

    /* A: load g_h 128x64 fp32, bf16-split, packed store (hi w0-31, lo w32-63) */
#pragma unroll
    for (int j = 0; j < 8; j++) {
        int f = tid + 256 * j;
        int row = f >> 4, kq = f & 15;      /* float4 index, k = 4*kq */
        int gr = m0 + row; if (gr >= M_ROWS) gr = M_ROWS - 1;
        float4 v = *(const float4*)(g_h + (size_t)gr * R_DIM + kq * 4);
        unsigned hw0, lw0, hw1, lw1;
        bfsplit2(v.x, v.y, hw0, lw0);
        bfsplit2(v.z, v.w, hw1, lw1);
        int g  = kq >> 1;                   /* hi granule 0..7 */
        int wo = (kq & 1) * 2;              /* word offset in granule */
        int bh_ = row * 64 + (( g      ^ (row & 7)) << 2) + wo;
        int bl_ = row * 64 + (((g + 8) ^ (row & 7)) << 2) + wo;
        As[bh_] = hw0; As[bh_ + 1] = hw1;
        As[bl_] = lw0; As[bl_ + 1] = lw1;
    }
    loadB(0, Br0);
    CP_COMMIT();

    for (int nb = 0; nb < 12; nb++) {
        if (nb < 11) {
            loadB(nb + 1, (nb & 1) ? Br0 : Br1);
            CP_COMMIT();
            CP_WAIT1();
        } else {
            CP_WAIT0();
        }
        __syncthreads();
        const unsigned* Bc = (nb & 1) ? Br1 : Br0;

        float acc[2][4][4];
#pragma unroll
        for (int mt = 0; mt < 2; mt++)
#pragma unroll
            for (int nt = 0; nt < 4; nt++)
#pragma unroll
                for (int i = 0; i < 4; i++) acc[mt][nt][i] = 0.0f;

#pragma unroll
        for (int kk = 0; kk < 4; kk++) {
            const int p0 = ((kk * 2)     ^ r4) << 2;
            const int p1 = ((kk * 2 + 1) ^ r4) << 2;
            unsigned ah[2][4], al[2][4], bh[4][2], bl[4][2];
#pragma unroll
            for (int mt = 0; mt < 2; mt++) {
                ah[mt][0] = As[arow[2*mt]   + p0];
                ah[mt][1] = As[arow[2*mt+1] + p0];
                ah[mt][2] = As[arow[2*mt]   + p1];
                ah[mt][3] = As[arow[2*mt+1] + p1];
                al[mt][0] = As[arow[2*mt]   + p0 + 32];
                al[mt][1] = As[arow[2*mt+1] + p0 + 32];
                al[mt][2] = As[arow[2*mt]   + p1 + 32];
                al[mt][3] = As[arow[2*mt+1] + p1 + 32];
            }
#pragma unroll
            for (int nt = 0; nt < 4; nt++) {
                bh[nt][0] = Bc[bbi[nt] + p0];
                bh[nt][1] = Bc[bbi[nt] + p1];
                bl[nt][0] = Bc[bbi[nt] + p0 + 32];
                bl[nt][1] = Bc[bbi[nt] + p1 + 32];
            }
#pragma unroll
            for (int mt = 0; mt < 2; mt++)
#pragma unroll
                for (int nt = 0; nt < 4; nt++) {
                    MMA_BF16(acc[mt][nt], al[mt], bh[nt]);
                    MMA_BF16(acc[mt][nt], ah[mt], bl[nt]);
                    MMA_BF16(acc[mt][nt], ah[mt], bh[nt]);
                }
        }

        /* epilogue for this n-block */
        int n0 = nb * 64;
#pragma unroll
        for (int mt = 0; mt < 2; mt++) {
            int row0 = m0 + wm * 32 + mt * 16 + r4;
#pragma unroll
            for (int nt = 0; nt < 4; nt++) {
                int col = n0 + wn * 32 + nt * 8 + 2 * c4;
                float g0 = __ldg(gamma + col);
                float g1 = __ldg(gamma + col + 1);
                if (row0 < M_ROWS) {
                    float2 o;
                    o.x = acc[mt][nt][0] * g0;
                    o.y = acc[mt][nt][1] * g1;
                    *(float2*)(out + (size_t)row0 * D_DIM + col) = o;
                }
                if (row0 + 8 < M_ROWS) {
                    float2 o;
                    o.x = acc[mt][nt][2] * g0;
                    o.y = acc[mt][nt][3] * g1;
                    *(float2*)(out + (size_t)(row0 + 8) * D_DIM + col) = o;
                }
            }
        }
        __syncthreads();
    }
}

/* ------------------------------------------------------------------ */
extern "C" void kernel_launch(void* const* d_in, const int* in_sizes, int n_in,
                              void* d_out, int out_size) {
    const float* x     = (const float*)d_in[0];
    const float* Wd    = (const float*)d_in[1];
    const float* Wg    = (const float*)d_in[2];
    const float* We    = (const float*)d_in[3];
    const float* be    = (const float*)d_in[4];
    const float* Wu    = (const float*)d_in[5];
    const float* gamma = (const float*)d_in[6];
    float* out = (float*)d_out;

    cudaFuncSetAttribute(k3_gemm_out,
                         cudaFuncAttributeMaxDynamicSharedMemorySize, K3_SMEM);

    k0_transpose<<<64, 256>>>(We);
    k0b_convert<<<24, 256>>>(Wu);
    k1_fused<<<(M_ROWS + 127) / 128, 256>>>(x, Wd, Wg, be);
    k3_gemm_out<<<(M_ROWS + 127) / 128, 256, K3_SMEM>>>(gamma, out);
}

// round 8
// speedup vs baseline: 2.1124x; 1.2171x over previous
#include <cuda_runtime.h>
#include <cuda_bf16.h>
#include <math.h>

#define D_DIM   768
#define R_DIM   64
#define E_NUM   4
#define NT      1029
#define BATCH   64
#define M_ROWS  (BATCH * NT)        /* 65856 */

/* scratch: "full" buffer, transposed expert weights, pre-split packed Wu */
__device__ float    g_h[(size_t)M_ROWS * R_DIM];
__device__ float    g_WeT[E_NUM * R_DIM * R_DIM];
__device__ unsigned g_WuP[D_DIM * 64];   /* [d][64w]: hi words 0-31, lo 32-63 */

__device__ __forceinline__ float gelu_exact(float v) {
    return 0.5f * v * (1.0f + erff(v * 0.70710678118654752f));
}

/* bf16 split+pack: two floats -> hi word (bf16x2) + lo word (residual) */
__device__ __forceinline__ void bfsplit2(float f0, float f1,
                                         unsigned& hw, unsigned& lw) {
    __nv_bfloat16 h0 = __float2bfloat16_rn(f0);
    __nv_bfloat16 h1 = __float2bfloat16_rn(f1);
    float r0 = f0 - __bfloat162float(h0);
    float r1 = f1 - __bfloat162float(h1);
    __nv_bfloat16 l0 = __float2bfloat16_rn(r0);
    __nv_bfloat16 l1 = __float2bfloat16_rn(r1);
    __nv_bfloat162 hv = __halves2bfloat162(h0, h1);
    __nv_bfloat162 lv = __halves2bfloat162(l0, l1);
    hw = *(unsigned*)&hv;
    lw = *(unsigned*)&lv;
}

#define MMA_BF16(C, A, B)                                                     \
    asm volatile(                                                             \
        "mma.sync.aligned.m16n8k16.row.col.f32.bf16.bf16.f32 "                \
        "{%0,%1,%2,%3}, {%4,%5,%6,%7}, {%8,%9}, {%0,%1,%2,%3};"               \
        : "+f"((C)[0]), "+f"((C)[1]), "+f"((C)[2]), "+f"((C)[3])              \
        : "r"((A)[0]), "r"((A)[1]), "r"((A)[2]), "r"((A)[3]),                 \
          "r"((B)[0]), "r"((B)[1]))

__device__ __forceinline__ void cp16(void* smem, const void* g) {
    unsigned sa = (unsigned)__cvta_generic_to_shared(smem);
    asm volatile("cp.async.ca.shared.global [%0], [%1], 16;" :: "r"(sa), "l"(g));
}
#define CP_COMMIT() asm volatile("cp.async.commit_group;")
#define CP_WAIT1()  asm volatile("cp.async.wait_group 1;")
#define CP_WAIT0()  asm volatile("cp.async.wait_group 0;")

/* ------------------------------------------------------------------ */
/* K0: WeT[e][r][s] = We[e][s][r]                                      */
__global__ void k0_transpose(const float* __restrict__ We) {
    int i = blockIdx.x * 256 + threadIdx.x;
    if (i < E_NUM * R_DIM * R_DIM) {
        int e = i >> 12;
        int r = (i >> 6) & 63;
        int s = i & 63;
        g_WeT[i] = We[(e << 12) + (s << 6) + r];
    }
}

/* K0b: Wu[d][64] fp32 -> g_WuP[d][64w] packed bf16 hi/lo               */
__global__ void k0b_convert(const float* __restrict__ Wu) {
    int i = blockIdx.x * 256 + threadIdx.x;   /* granule id: 768*8 */
    if (i >= D_DIM * 8) return;
    int d = i >> 3;
    int g = i & 7;
    const float* src = Wu + d * 64 + g * 8;
    float4 v0 = *(const float4*)(src);
    float4 v1 = *(const float4*)(src + 4);
    unsigned h0,l0,h1,l1,h2,l2,h3,l3;
    bfsplit2(v0.x, v0.y, h0, l0);
    bfsplit2(v0.z, v0.w, h1, l1);
    bfsplit2(v1.x, v1.y, h2, l2);
    bfsplit2(v1.z, v1.w, h3, l3);
    unsigned* dst = g_WuP + d * 64;
    *(uint4*)(dst + g * 4)      = make_uint4(h0, h1, h2, h3);
    *(uint4*)(dst + 32 + g * 4) = make_uint4(l0, l1, l2, l3);
}

/* ------------------------------------------------------------------ */
/* K1 fused (3-term bf16): h = gelu(X.Wd^T) + top-1 MoE -> g_h.        */
/* 128(M)x64(N), K-step 32. LDG->bfsplit->packed STS, dbl-buffered.    */
#define HS 66
__global__ __launch_bounds__(256, 2) void k1_fused(
    const float* __restrict__ X, const float* __restrict__ Wd,
    const float* __restrict__ Wg, const float* __restrict__ be)
{
    __shared__ __align__(16) unsigned s_buf[12288];  /* 48 KB */
    unsigned* Xp0 = s_buf;            /* 128 rows x 32 words */
    unsigned* Xp1 = s_buf + 4096;
    unsigned* Wp0 = s_buf + 8192;     /* 64 rows x 32 words  */
    unsigned* Wp1 = s_buf + 10240;
    float*    Hs  = (float*)s_buf;    /* reuse post-GEMM: 128*66 */

    const int tid  = threadIdx.x;
    const int wid  = tid >> 5;
    const int lane = tid & 31;
    const int wm   = wid >> 1;
    const int wn   = wid & 1;
    const int r4   = lane >> 2;
    const int c4   = lane & 3;
    const int m0   = blockIdx.x * 128;

    /* LDG assignments */
    int xrow[4], xkq[4];
    const float* xptr[4];
#pragma unroll
    for (int j = 0; j < 4; j++) {
        int f = tid + 256 * j;
        xrow[j] = f >> 3; xkq[j] = f & 7;
        int gr = m0 + xrow[j]; if (gr >= M_ROWS) gr = M_ROWS - 1;
        xptr[j] = X + (size_t)gr * D_DIM + xkq[j] * 4;
    }
    int wrow[2], wkq[2];
    const float* wptr[2];
#pragma unroll
    for (int j = 0; j < 2; j++) {
        int f = tid + 256 * j;
        wrow[j] = f >> 3; wkq[j] = f & 7;
        wptr[j] = Wd + wrow[j] * D_DIM + wkq[j] * 4;
    }

    /* fragment base indices */
    int arow[4], bbi[4];
#pragma unroll
    for (int i = 0; i < 4; i++)
        arow[i] = (wm * 32 + r4 + i * 8) * 32 + c4;
#pragma unroll
    for (int nt = 0; nt < 4; nt++)
        bbi[nt] = (wn * 32 + nt * 8 + r4) * 32 + c4;

    float acc[2][4][4];
#pragma unroll
    for (int mt = 0; mt < 2; mt++)
#pragma unroll
        for (int nt = 0; nt < 4; nt++)
#pragma unroll
            for (int i = 0; i < 4; i++) acc[mt][nt][i] = 0.0f;

    float4 xv[4], wv[2];
#pragma unroll
    for (int j = 0; j < 4; j++) xv[j] = *(const float4*)(xptr[j]);
#pragma unroll
    for (int j = 0; j < 2; j++) wv[j] = *(const float4*)(wptr[j]);

    for (int it = 0; it < 24; it++) {
        unsigned* Xp = (it & 1) ? Xp1 : Xp0;
        unsigned* Wp = (it & 1) ? Wp1 : Wp0;

        /* convert + packed store (hi granules 0-3, lo granules 4-7) */
#pragma unroll
        for (int j = 0; j < 4; j++) {
            unsigned hw0, lw0, hw1, lw1;
            bfsplit2(xv[j].x, xv[j].y, hw0, lw0);
            bfsplit2(xv[j].z, xv[j].w, hw1, lw1);
            int row = xrow[j], kq = xkq[j];
            int g   = kq >> 1;
            int wo  = (kq & 1) * 2;
            int bh_ = row * 32 + (( g      ^ (row & 7)) << 2) + wo;
            int bl_ = row * 32 + (((g + 4) ^ (row & 7)) << 2) + wo;
            Xp[bh_] = hw0; Xp[bh_ + 1] = hw1;
            Xp[bl_] = lw0; Xp[bl_ + 1] = lw1;
        }
#pragma unroll
        for (int j = 0; j < 2; j++) {
            unsigned hw0, lw0, hw1, lw1;
            bfsplit2(wv[j].x, wv[j].y, hw0, lw0);
            bfsplit2(wv[j].z, wv[j].w, hw1, lw1);
            int row = wrow[j], kq = wkq[j];
            int g   = kq >> 1;
            int wo  = (kq & 1) * 2;
            int bh_ = row * 32 + (( g      ^ (row & 7)) << 2) + wo;
            int bl_ = row * 32 + (((g + 4) ^ (row & 7)) << 2) + wo;
            Wp[bh_] = hw0; Wp[bh_ + 1] = hw1;
            Wp[bl_] = lw0; Wp[bl_ + 1] = lw1;
        }

        /* prefetch next k-tile into registers */
        if (it < 23) {
            int kt = (it + 1) * 32;
#pragma unroll
            for (int j = 0; j < 4; j++) xv[j] = *(const float4*)(xptr[j] + kt);
#pragma unroll
            for (int j = 0; j < 2; j++) wv[j] = *(const float4*)(wptr[j] + kt);
        }
        __syncthreads();

#pragma unroll
        for (int kk = 0; kk < 2; kk++) {
            const int p0  = ((kk * 2)     ^ r4) << 2;
            const int p1  = ((kk * 2 + 1) ^ r4) << 2;
            const int q0  = ((kk * 2 + 4) ^ r4) << 2;
            const int q1  = ((kk * 2 + 5) ^ r4) << 2;
            unsigned ah[2][4], al[2][4], bh[4][2], bl[4][2];
#pragma unroll
            for (int mt = 0; mt < 2; mt++) {
                ah[mt][0] = Xp[arow[2*mt]   + p0];
                ah[mt][1] = Xp[arow[2*mt+1] + p0];
                ah[mt][2] = Xp[arow[2*mt]   + p1];
                ah[mt][3] = Xp[arow[2*mt+1] + p1];
                al[mt][0] = Xp[arow[2*mt]   + q0];
                al[mt][1] = Xp[arow[2*mt+1] + q0];
                al[mt][2] = Xp[arow[2*mt]   + q1];
                al[mt][3] = Xp[arow[2*mt+1] + q1];
            }
#pragma unroll
            for (int nt = 0; nt < 4; nt++) {
                bh[nt][0] = Wp[bbi[nt] + p0];
                bh[nt][1] = Wp[bbi[nt] + p1];
                bl[nt][0] = Wp[bbi[nt] + q0];
                bl[nt][1] = Wp[bbi[nt] + q1];
            }
#pragma unroll
            for (int mt = 0; mt < 2; mt++)
#pragma unroll
                for (int nt = 0; nt < 4; nt++) {
                    MMA_BF16(acc[mt][nt], al[mt], bh[nt]);
                    MMA_BF16(acc[mt][nt], ah[mt], bl[nt]);
                    MMA_BF16(acc[mt][nt], ah[mt], bh[nt]);
                }
        }
    }
    __syncthreads();   /* all MMA reads done before s_buf reuse as Hs */

    /* ---- epilogue phase 1: gelu -> Hs (smem), stride 66 ---- */
#pragma unroll
    for (int mt = 0; mt < 2; mt++) {
        int lr = wm * 32 + mt * 16 + r4;
#pragma unroll
        for (int nt = 0; nt < 4; nt++) {
            int col = wn * 32 + nt * 8 + 2 * c4;
            Hs[lr * HS + col]           = gelu_exact(acc[mt][nt][0]);
            Hs[lr * HS + col + 1]       = gelu_exact(acc[mt][nt][1]);
            Hs[(lr + 8) * HS + col]     = gelu_exact(acc[mt][nt][2]);
            Hs[(lr + 8) * HS + col + 1] = gelu_exact(acc[mt][nt][3]);
        }
    }
    __syncthreads();

    /* ---- epilogue phase 2: per-token MoE, write final to g_h ---- */
    for (int grp = 0; grp < 4; grp++) {
        const int tb = wid * 16 + grp * 4;

        int   esel[4];
        float wsel[4];
        int   grow[4];
        int   vmoe[4];
#pragma unroll
        for (int j = 0; j < 4; j++) {
            int t = tb + j;
            int gr = m0 + t;
            grow[j] = gr;
            if (gr >= M_ROWS) { vmoe[j] = 0; }
            else {
                int bidx = gr / NT;
                int nidx = gr - bidx * NT;
                vmoe[j] = (nidx >= 5) ? 2 : 1;
            }
            float h0 = Hs[t * HS + lane];
            float h1 = Hs[t * HS + 32 + lane];
            float l0 = h0 * __ldg(Wg + lane)       + h1 * __ldg(Wg + 32 + lane);
            float l1 = h0 * __ldg(Wg + 64 + lane)  + h1 * __ldg(Wg + 96 + lane);
            float l2 = h0 * __ldg(Wg + 128 + lane) + h1 * __ldg(Wg + 160 + lane);
            float l3 = h0 * __ldg(Wg + 192 + lane) + h1 * __ldg(Wg + 224 + lane);
#pragma unroll
            for (int o = 16; o > 0; o >>= 1) {
                l0 += __shfl_xor_sync(0xffffffffu, l0, o);
                l1 += __shfl_xor_sync(0xffffffffu, l1, o);
                l2 += __shfl_xor_sync(0xffffffffu, l2, o);
                l3 += __shfl_xor_sync(0xffffffffu, l3, o);
            }
            float mx = fmaxf(fmaxf(l0, l1), fmaxf(l2, l3));
            float e0 = __expf(l0 - mx);
            float e1 = __expf(l1 - mx);
            float e2 = __expf(l2 - mx);
            float e3 = __expf(l3 - mx);
            float ssum = e0 + e1 + e2 + e3;
            int am = 0; float bv = l0; float ev = e0;
            if (l1 > bv) { bv = l1; am = 1; ev = e1; }
            if (l2 > bv) { bv = l2; am = 2; ev = e2; }
            if (l3 > bv) { bv = l3; am = 3; ev = e3; }
            esel[j] = am;
            wsel[j] = ev / ssum;
        }

        float acc2[4][2];
#pragma unroll
        for (int j = 0; j < 4; j++) { acc2[j][0] = 0.0f; acc2[j][1] = 0.0f; }
        const float* wp[4];
#pragma unroll
        for (int j = 0; j < 4; j++) wp[j] = g_WeT + (esel[j] << 12);

#pragma unroll 8
        for (int r = 0; r < 64; r++) {
#pragma unroll
            for (int j = 0; j < 4; j++) {
                float hr = Hs[(tb + j) * HS + r];
                float2 wv2 = *(const float2*)(wp[j] + (r << 6) + lane * 2);
                acc2[j][0] = fmaf(hr, wv2.x, acc2[j][0]);
                acc2[j][1] = fmaf(hr, wv2.y, acc2[j][1]);
            }
        }

#pragma unroll
        for (int j = 0; j < 4; j++) {
            if (vmoe[j] == 0) continue;
            int t = tb + j;
            int e = esel[j];
            float s = (vmoe[j] == 2) ? wsel[j] : 0.0f;
            float b0 = __ldg(be + (e << 6) + lane * 2);
            float b1 = __ldg(be + (e << 6) + lane * 2 + 1);
            float2 hv;
            hv.x = Hs[t * HS + lane * 2];
            hv.y = Hs[t * HS + lane * 2 + 1];
            float2 o;
            o.x = hv.x + s * (acc2[j][0] + b0);
            o.y = hv.y + s * (acc2[j][1] + b1);
            *(float2*)(g_h + (size_t)grow[j] * R_DIM + lane * 2) = o;
        }
    }
}

/* ------------------------------------------------------------------ */
/* K3 (3-term bf16 m16n8k16): out = (full . Wu^T) * gamma              */
#define K3_SMEM (64 * 1024)
__global__ __launch_bounds__(256, 2) void k3_gemm_out(
    const float* __restrict__ gamma, float* __restrict__ out)
{
    extern __shared__ __align__(16) unsigned dsm[];
    unsigned* As  = dsm;              /* 128 rows x 64 words = 32 KB */
    unsigned* Br0 = dsm + 8192;       /* 64 rows x 64 words = 16 KB  */
    unsigned* Br1 = dsm + 12288;

    const int tid  = threadIdx.x;
    const int wid  = tid >> 5;
    const int lane = tid & 31;
    const int wm   = wid >> 1;
    const int wn   = wid & 1;
    const int r4   = lane >> 2;
    const int c4   = lane & 3;
    const int m0   = blockIdx.x * 128;

    int arow[4], bbi[4];
#pragma unroll
    for (int i = 0; i < 4; i++)
        arow[i] = (wm * 32 + r4 + i * 8) * 64 + c4;
#pragma unroll
    for (int nt = 0; nt < 4; nt++)
        bbi[nt] = (wn * 32 + nt * 8 + r4) * 64 + c4;

    auto loadB = [&](int nb, unsigned* buf) {
#pragma unroll
        for (int j = 0; j < 4; j++) {
            int f = tid + 256 * j;
            int row = f >> 4, g = f & 15;
            cp16(buf + row * 64 + ((g ^ (row & 7)) << 2),
                 g_WuP + (size_t)(nb * 64 + row) * 64 + g * 4);
        }
    };

#pragma unroll
    for (int j = 0; j < 8; j++) {
        int f = tid + 256 * j;
        int row = f >> 4, kq = f & 15;
        int gr = m0 + row; if (gr >= M_ROWS) gr = M_ROWS - 1;
        float4 v = *(const float4*)(g_h + (size_t)gr * R_DIM + kq * 4);
        unsigned hw0, lw0, hw1, lw1;
        bfsplit2(v.x, v.y, hw0, lw0);
        bfsplit2(v.z, v.w, hw1, lw1);
        int g  = kq >> 1;
        int wo = (kq & 1) * 2;
        int bh_ = row * 64 + (( g      ^ (row & 7)) << 2) + wo;
        int bl_ = row * 64 + (((g + 8) ^ (row & 7)) << 2) + wo;
        As[bh_] = hw0; As[bh_ + 1] = hw1;
        As[bl_] = lw0; As[bl_ + 1] = lw1;
    }
    loadB(0, Br0);
    CP_COMMIT();

    for (int nb = 0; nb < 12; nb++) {
        if (nb < 11) {
            loadB(nb + 1, (nb & 1) ? Br0 : Br1);
            CP_COMMIT();
            CP_WAIT1();
        } else {
            CP_WAIT0();
        }
        __syncthreads();
        const unsigned* Bc = (nb & 1) ? Br1 : Br0;

        float acc[2][4][4];
#pragma unroll
        for (int mt = 0; mt < 2; mt++)
#pragma unroll
            for (int nt = 0; nt < 4; nt++)
#pragma unroll
                for (int i = 0; i < 4; i++) acc[mt][nt][i] = 0.0f;

#pragma unroll
        for (int kk = 0; kk < 4; kk++) {
            const int p0 = ((kk * 2)     ^ r4) << 2;
            const int p1 = ((kk * 2 + 1) ^ r4) << 2;
            unsigned ah[2][4], al[2][4], bh[4][2], bl[4][2];
#pragma unroll
            for (int mt = 0; mt < 2; mt++) {
                ah[mt][0] = As[arow[2*mt]   + p0];
                ah[mt][1] = As[arow[2*mt+1] + p0];
                ah[mt][2] = As[arow[2*mt]   + p1];
                ah[mt][3] = As[arow[2*mt+1] + p1];
                al[mt][0] = As[arow[2*mt]   + p0 + 32];
                al[mt][1] = As[arow[2*mt+1] + p0 + 32];
                al[mt][2] = As[arow[2*mt]   + p1 + 32];
                al[mt][3] = As[arow[2*mt+1] + p1 + 32];
            }
#pragma unroll
            for (int nt = 0; nt < 4; nt++) {
                bh[nt][0] = Bc[bbi[nt] + p0];
                bh[nt][1] = Bc[bbi[nt] + p1];
                bl[nt][0] = Bc[bbi[nt] + p0 + 32];
                bl[nt][1] = Bc[bbi[nt] + p1 + 32];
            }
#pragma unroll
            for (int mt = 0; mt < 2; mt++)
#pragma unroll
                for (int nt = 0; nt < 4; nt++) {
                    MMA_BF16(acc[mt][nt], al[mt], bh[nt]);
                    MMA_BF16(acc[mt][nt], ah[mt], bl[nt]);
                    MMA_BF16(acc[mt][nt], ah[mt], bh[nt]);
                }
        }

        int n0 = nb * 64;
#pragma unroll
        for (int mt = 0; mt < 2; mt++) {
            int row0 = m0 + wm * 32 + mt * 16 + r4;
#pragma unroll
            for (int nt = 0; nt < 4; nt++) {
                int col = n0 + wn * 32 + nt * 8 + 2 * c4;
                float g0 = __ldg(gamma + col);
                float g1 = __ldg(gamma + col + 1);
                if (row0 < M_ROWS) {
                    float2 o;
                    o.x = acc[mt][nt][0] * g0;
                    o.y = acc[mt][nt][1] * g1;
                    *(float2*)(out + (size_t)row0 * D_DIM + col) = o;
                }
                if (row0 + 8 < M_ROWS) {
                    float2 o;
                    o.x = acc[mt][nt][2] * g0;
                    o.y = acc[mt][nt][3] * g1;
                    *(float2*)(out + (size_t)(row0 + 8) * D_DIM + col) = o;
                }
            }
        }
        __syncthreads();
    }
}

/* ------------------------------------------------------------------ */
extern "C" void kernel_launch(void* const* d_in, const int* in_sizes, int n_in,
                              void* d_out, int out_size) {
    const float* x     = (const float*)d_in[0];
    const float* Wd    = (const float*)d_in[1];
    const float* Wg    = (const float*)d_in[2];
    const float* We    = (const float*)d_in[3];
    const float* be    = (const float*)d_in[4];
    const float* Wu    = (const float*)d_in[5];
    const float* gamma = (const float*)d_in[6];
    float* out = (float*)d_out;

    cudaFuncSetAttribute(k3_gemm_out,
                         cudaFuncAttributeMaxDynamicSharedMemorySize, K3_SMEM);

    k0_transpose<<<64, 256>>>(We);
    k0b_convert<<<24, 256>>>(Wu);
    k1_fused<<<(M_ROWS + 127) / 128, 256>>>(x, Wd, Wg, be);
    k3_gemm_out<<<(M_ROWS + 127) / 128, 256, K3_SMEM>>>(gamma, out);
}